// round 8
// baseline (speedup 1.0000x reference)
#include <cuda_runtime.h>
#include <cstdint>

// ---------------------------------------------------------------------------
// QThreeLayer: 6-bit quantized MLP 16 -> 64 -> 32 -> 32 -> 5, softmax.
// dp4a integer emulation, each layer computed exactly once.
// Round 8: inter-phase accumulators stored TRANSPOSED [chunk][row] so all
// intermediate STG/LDG are fully coalesced (4 wavefronts, not 32).
// ---------------------------------------------------------------------------

#define ROWS_CAP (1 << 20)

// ---- persistent device state (reset every replay by k0_init) --------------
__device__ unsigned int g_xmax;
__device__ unsigned int g_hmax1, g_hmax2, g_hmax3;  // float-as-uint, >= 0

__device__ int g_W1p[64 * 4];   // packed int8x4 weights, [o][k]
__device__ int g_W2p[32 * 16];
__device__ int g_W3p[32 * 8];
__device__ int g_W4p[8 * 8];    // padded to 8 rows for alignment
__device__ float g_wsc1[64], g_wsc2[32], g_wsc3[32], g_wsc4[5];

__device__ float g_sf0, g_inv0;
__device__ float g_sf1, g_sf2, g_sf3;
__device__ float g_bsf1[64], g_bsf2[32], g_bsf3[32], g_bsf4[5];
__device__ float g_cmb1[64], g_cmb2[32], g_cmb3[32];  // bsf/sf combined
__device__ int g_bint1[64], g_bint2[32], g_bint3[32], g_bint4[5];

// inter-phase accumulators, TRANSPOSED: element [c * ROWS_CAP + row]
__device__ uint4 g_a1[8 * ROWS_CAP];  // L1 accs int16 pairs
__device__ uint4 g_a2[8 * ROWS_CAP];  // L2 accs int32
__device__ uint4 g_a3[4 * ROWS_CAP];  // L3 accs int16 pairs

// ---- helpers ---------------------------------------------------------------
__device__ __forceinline__ int dp4a_(int a, int b, int c) {
    int d;
    asm("dp4a.s32.s32 %0, %1, %2, %3;" : "=r"(d) : "r"(a), "r"(b), "r"(c));
    return d;
}
__device__ __forceinline__ int iclamp(int v, int lo, int hi) {
    return v < lo ? lo : (v > hi ? hi : v);
}
__device__ __forceinline__ int pack4i(int a, int b, int c, int d) {
    return (a & 0xFF) | ((b & 0xFF) << 8) | ((c & 0xFF) << 16) | ((d & 0xFF) << 24);
}
__device__ __forceinline__ int lo16(unsigned u) { return (int)(u << 16) >> 16; }
__device__ __forceinline__ int hi16(unsigned u) { return (int)u >> 16; }

// round(t/s) with clip to [-32,31]; reciprocal fast path + exact IEEE
// fallback near .5 boundaries.
__device__ __forceinline__ int fquant(float t, float inv, float s) {
    float u = t * inv;
    float qa = rintf(u);
    if (0.5f - fabsf(u - qa) < 2e-5f) qa = rintf(__fdiv_rn(t, s));
    return iclamp((int)qa, -32, 31);
}

// quantize relu(acc*bsf)/sf; cb.x = bsf/sf (fast), cb.y = bsf (exact path)
__device__ __forceinline__ int fquant_pos2(float accf, float2 cb, float sf) {
    float u = fmaxf(accf * cb.x, 0.f);
    float qa = rintf(u);
    if (0.5f - fabsf(u - qa) < 2e-5f) {
        float h = fmaxf(__fmul_rn(accf, cb.y), 0.f);
        qa = rintf(__fdiv_rn(h, sf));
    }
    int q = (int)qa;
    return q > 31 ? 31 : q;
}

// quantize 4 int16-acc channels (two packed uints) into one int8x4 word
__device__ __forceinline__ int quant4_i16(unsigned u0, unsigned u1, int ob,
                                          const float2* scf, float sf) {
    int a = fquant_pos2((float)lo16(u0), scf[ob + 0], sf);
    int b = fquant_pos2((float)hi16(u0), scf[ob + 1], sf);
    int c = fquant_pos2((float)lo16(u1), scf[ob + 2], sf);
    int d = fquant_pos2((float)hi16(u1), scf[ob + 3], sf);
    return pack4i(a, b, c, d);
}

__device__ __forceinline__ void warp_fmax_atomic(float m, unsigned* dst) {
#pragma unroll
    for (int s = 16; s; s >>= 1) m = fmaxf(m, __shfl_xor_sync(0xffffffffu, m, s));
    if ((threadIdx.x & 31) == 0) atomicMax(dst, __float_as_uint(m));
}

// ---- K0: reset reductions + quantize weights ------------------------------
__global__ void k0_init(const float* __restrict__ W1, const float* __restrict__ W2,
                        const float* __restrict__ W3, const float* __restrict__ W4) {
    int t = threadIdx.x;
    if (t == 0) { g_xmax = 0u; g_hmax1 = 0u; g_hmax2 = 0u; g_hmax3 = 0u; }
    if (t < 24) g_W4p[40 + t] = 0;  // pad

    if (t < 64) {  // layer 1: [64,16]
        const float* w = W1 + t * 16;
        float m = 0.f;
#pragma unroll
        for (int i = 0; i < 16; i++) m = fmaxf(m, fabsf(w[i]));
        float sc = __fdiv_rn(fmaxf(m, 1e-8f), 31.0f);
        g_wsc1[t] = sc;
#pragma unroll
        for (int k = 0; k < 4; k++) {
            int a = iclamp((int)rintf(__fdiv_rn(w[4 * k + 0], sc)), -32, 31);
            int b = iclamp((int)rintf(__fdiv_rn(w[4 * k + 1], sc)), -32, 31);
            int c = iclamp((int)rintf(__fdiv_rn(w[4 * k + 2], sc)), -32, 31);
            int d = iclamp((int)rintf(__fdiv_rn(w[4 * k + 3], sc)), -32, 31);
            g_W1p[t * 4 + k] = pack4i(a, b, c, d);
        }
    } else if (t < 96) {  // layer 2: [32,64]
        int o = t - 64;
        const float* w = W2 + o * 64;
        float m = 0.f;
#pragma unroll
        for (int i = 0; i < 64; i++) m = fmaxf(m, fabsf(w[i]));
        float sc = __fdiv_rn(fmaxf(m, 1e-8f), 31.0f);
        g_wsc2[o] = sc;
#pragma unroll
        for (int k = 0; k < 16; k++) {
            int a = iclamp((int)rintf(__fdiv_rn(w[4 * k + 0], sc)), -32, 31);
            int b = iclamp((int)rintf(__fdiv_rn(w[4 * k + 1], sc)), -32, 31);
            int c = iclamp((int)rintf(__fdiv_rn(w[4 * k + 2], sc)), -32, 31);
            int d = iclamp((int)rintf(__fdiv_rn(w[4 * k + 3], sc)), -32, 31);
            g_W2p[o * 16 + k] = pack4i(a, b, c, d);
        }
    } else if (t < 128) {  // layer 3: [32,32]
        int o = t - 96;
        const float* w = W3 + o * 32;
        float m = 0.f;
#pragma unroll
        for (int i = 0; i < 32; i++) m = fmaxf(m, fabsf(w[i]));
        float sc = __fdiv_rn(fmaxf(m, 1e-8f), 31.0f);
        g_wsc3[o] = sc;
#pragma unroll
        for (int k = 0; k < 8; k++) {
            int a = iclamp((int)rintf(__fdiv_rn(w[4 * k + 0], sc)), -32, 31);
            int b = iclamp((int)rintf(__fdiv_rn(w[4 * k + 1], sc)), -32, 31);
            int c = iclamp((int)rintf(__fdiv_rn(w[4 * k + 2], sc)), -32, 31);
            int d = iclamp((int)rintf(__fdiv_rn(w[4 * k + 3], sc)), -32, 31);
            g_W3p[o * 8 + k] = pack4i(a, b, c, d);
        }
    } else if (t < 133) {  // layer 4: [5,32]
        int o = t - 128;
        const float* w = W4 + o * 32;
        float m = 0.f;
#pragma unroll
        for (int i = 0; i < 32; i++) m = fmaxf(m, fabsf(w[i]));
        float sc = __fdiv_rn(fmaxf(m, 1e-8f), 31.0f);
        g_wsc4[o] = sc;
#pragma unroll
        for (int k = 0; k < 8; k++) {
            int a = iclamp((int)rintf(__fdiv_rn(w[4 * k + 0], sc)), -32, 31);
            int b = iclamp((int)rintf(__fdiv_rn(w[4 * k + 1], sc)), -32, 31);
            int c = iclamp((int)rintf(__fdiv_rn(w[4 * k + 2], sc)), -32, 31);
            int d = iclamp((int)rintf(__fdiv_rn(w[4 * k + 3], sc)), -32, 31);
            g_W4p[o * 8 + k] = pack4i(a, b, c, d);
        }
    }
}

// ---- K1: global max|x| -----------------------------------------------------
__global__ void k1_absmax(const float* __restrict__ x, int n4) {
    const float4* x4 = (const float4*)x;
    int i = blockIdx.x * blockDim.x + threadIdx.x;
    int stride = gridDim.x * blockDim.x;
    float m = 0.f;
    for (; i < n4; i += stride) {
        float4 v = x4[i];
        m = fmaxf(m, fmaxf(fmaxf(fabsf(v.x), fabsf(v.y)), fmaxf(fabsf(v.z), fabsf(v.w))));
    }
    warp_fmax_atomic(m, &g_xmax);
}

// ---- K1b: sf0, layer-1 bias quant -----------------------------------------
__global__ void k1b_fin(const float* __restrict__ b1) {
    __shared__ float ssf;
    int t = threadIdx.x;
    if (t == 0) {
        float sf = __fdiv_rn(fmaxf(__uint_as_float(g_xmax), 1e-8f), 31.0f);
        g_sf0 = sf;
        g_inv0 = __fdiv_rn(1.0f, sf);
        ssf = sf;
    }
    __syncthreads();
    if (t < 64) {
        float bsf = __fmul_rn(g_wsc1[t], ssf);
        g_bsf1[t] = bsf;
        g_bint1[t] = iclamp((int)rintf(__fdiv_rn(b1[t], bsf)), -32, 31);
    }
}

// ---- K2: x -> q0 (regs) -> L1, store acc1 i16 (transposed), h-max ---------
__global__ __launch_bounds__(256, 2) void k2_l1(const float* __restrict__ x,
                                                int rows, int nt) {
    __shared__ int4 sW[64];
    __shared__ int sb[64];
    __shared__ float sbsf[64], sc0[2];
    int t = threadIdx.x;
    if (t < 64) {
        sW[t] = ((const int4*)g_W1p)[t];
        sb[t] = g_bint1[t];
        sbsf[t] = g_bsf1[t];
    }
    if (t == 0) { sc0[0] = g_inv0; sc0[1] = g_sf0; }
    __syncthreads();
    float inv0 = sc0[0], sf0 = sc0[1];
    float m = 0.f;

    const float4* x4 = (const float4*)x;
#pragma unroll 1
    for (int row = blockIdx.x * 256 + t; row < rows; row += nt) {
        int qa[4];
#pragma unroll
        for (int j = 0; j < 4; j++) {
            float4 v = x4[(size_t)row * 4 + j];
            qa[j] = pack4i(fquant(v.x, inv0, sf0), fquant(v.y, inv0, sf0),
                           fquant(v.z, inv0, sf0), fquant(v.w, inv0, sf0));
        }
#pragma unroll
        for (int g = 0; g < 8; g++) {
            unsigned w[4];
#pragma unroll
            for (int j = 0; j < 4; j++) {
                int o0 = g * 8 + 2 * j, o1 = o0 + 1;
                int4 w0 = sW[o0], w1 = sW[o1];
                int a0 = sb[o0], a1 = sb[o1];
                a0 = dp4a_(qa[0], w0.x, a0); a0 = dp4a_(qa[1], w0.y, a0);
                a0 = dp4a_(qa[2], w0.z, a0); a0 = dp4a_(qa[3], w0.w, a0);
                a1 = dp4a_(qa[0], w1.x, a1); a1 = dp4a_(qa[1], w1.y, a1);
                a1 = dp4a_(qa[2], w1.z, a1); a1 = dp4a_(qa[3], w1.w, a1);
                m = fmaxf(m, __fmul_rn((float)a0, sbsf[o0]));
                m = fmaxf(m, __fmul_rn((float)a1, sbsf[o1]));
                w[j] = ((unsigned)a0 & 0xFFFFu) | ((unsigned)a1 << 16);
            }
            g_a1[(size_t)g * ROWS_CAP + row] = make_uint4(w[0], w[1], w[2], w[3]);
        }
    }
    warp_fmax_atomic(m, &g_hmax1);
}

// ---- K2b: sf1, cmb1, layer-2 bias quant -----------------------------------
__global__ void k2b_fin(const float* __restrict__ b2) {
    __shared__ float s_sf, s_inv;
    int t = threadIdx.x;  // 64 threads
    if (t == 0) {
        float sf = __fdiv_rn(fmaxf(__uint_as_float(g_hmax1), 1e-8f), 31.0f);
        g_sf1 = sf;
        s_sf = sf;
        s_inv = __fdiv_rn(1.0f, sf);
    }
    __syncthreads();
    g_cmb1[t] = __fmul_rn(g_bsf1[t], s_inv);
    if (t < 32) {
        float bsf = __fmul_rn(g_wsc2[t], s_sf);
        g_bsf2[t] = bsf;
        g_bint2[t] = iclamp((int)rintf(__fdiv_rn(b2[t], bsf)), -32, 31);
    }
}

// ---- K3: acc1 -> q1 -> L2, store acc2 i32 (transposed), h-max -------------
__global__ __launch_bounds__(256, 2) void k3_l2(int rows, int nt) {
    __shared__ int4 sW2[128];
    __shared__ int sb2[32];
    __shared__ float2 scf1[64];
    __shared__ float sbsf2[32], scc[1];
    int t = threadIdx.x;
    if (t < 128) sW2[t] = ((const int4*)g_W2p)[t];
    if (t < 64) scf1[t] = make_float2(g_cmb1[t], g_bsf1[t]);
    if (t < 32) { sb2[t] = g_bint2[t]; sbsf2[t] = g_bsf2[t]; }
    if (t == 0) scc[0] = g_sf1;
    __syncthreads();
    float sf1 = scc[0];
    float m = 0.f;

#pragma unroll 1
    for (int row = blockIdx.x * 256 + t; row < rows; row += nt) {
        int q1[16];
#pragma unroll
        for (int c = 0; c < 8; c++) {
            uint4 v = g_a1[(size_t)c * ROWS_CAP + row];
            q1[c * 2 + 0] = quant4_i16(v.x, v.y, c * 8 + 0, scf1, sf1);
            q1[c * 2 + 1] = quant4_i16(v.z, v.w, c * 8 + 4, scf1, sf1);
        }
#pragma unroll
        for (int g = 0; g < 8; g++) {
            int w[4];
#pragma unroll
            for (int j = 0; j < 4; j++) {
                int o = g * 4 + j;
                int acc = sb2[o];
#pragma unroll
                for (int kk = 0; kk < 4; kk++) {
                    int4 wv = sW2[o * 4 + kk];
                    acc = dp4a_(q1[kk * 4 + 0], wv.x, acc);
                    acc = dp4a_(q1[kk * 4 + 1], wv.y, acc);
                    acc = dp4a_(q1[kk * 4 + 2], wv.z, acc);
                    acc = dp4a_(q1[kk * 4 + 3], wv.w, acc);
                }
                m = fmaxf(m, __fmul_rn((float)acc, sbsf2[o]));
                w[j] = acc;
            }
            g_a2[(size_t)g * ROWS_CAP + row] =
                make_uint4((unsigned)w[0], (unsigned)w[1], (unsigned)w[2], (unsigned)w[3]);
        }
    }
    warp_fmax_atomic(m, &g_hmax2);
}

// ---- K3b: sf2, cmb2, layer-3 bias quant -----------------------------------
__global__ void k3b_fin(const float* __restrict__ b3) {
    __shared__ float s_sf, s_inv;
    int t = threadIdx.x;  // 32 threads
    if (t == 0) {
        float sf = __fdiv_rn(fmaxf(__uint_as_float(g_hmax2), 1e-8f), 31.0f);
        g_sf2 = sf;
        s_sf = sf;
        s_inv = __fdiv_rn(1.0f, sf);
    }
    __syncthreads();
    g_cmb2[t] = __fmul_rn(g_bsf2[t], s_inv);
    {
        float bsf = __fmul_rn(g_wsc3[t], s_sf);
        g_bsf3[t] = bsf;
        g_bint3[t] = iclamp((int)rintf(__fdiv_rn(b3[t], bsf)), -32, 31);
    }
}

// ---- K4: acc2 -> q2 -> L3, store acc3 i16 (transposed), h-max -------------
__global__ __launch_bounds__(256, 2) void k4_l3(int rows, int nt) {
    __shared__ int4 sW3[64];
    __shared__ int sb3[32];
    __shared__ float2 scf2[32];
    __shared__ float sbsf3[32], scc[1];
    int t = threadIdx.x;
    if (t < 64) sW3[t] = ((const int4*)g_W3p)[t];
    if (t < 32) {
        scf2[t] = make_float2(g_cmb2[t], g_bsf2[t]);
        sb3[t] = g_bint3[t];
        sbsf3[t] = g_bsf3[t];
    }
    if (t == 0) scc[0] = g_sf2;
    __syncthreads();
    float sf2 = scc[0];
    float m = 0.f;

#pragma unroll 1
    for (int row = blockIdx.x * 256 + t; row < rows; row += nt) {
        int q2[8];
#pragma unroll
        for (int c = 0; c < 8; c++) {
            uint4 v = g_a2[(size_t)c * ROWS_CAP + row];
            int ob = c * 4;
            q2[c] = pack4i(
                fquant_pos2((float)(int)v.x, scf2[ob + 0], sf2),
                fquant_pos2((float)(int)v.y, scf2[ob + 1], sf2),
                fquant_pos2((float)(int)v.z, scf2[ob + 2], sf2),
                fquant_pos2((float)(int)v.w, scf2[ob + 3], sf2));
        }
#pragma unroll
        for (int g = 0; g < 4; g++) {
            unsigned w[4];
#pragma unroll
            for (int j = 0; j < 4; j++) {
                int o0 = g * 8 + 2 * j, o1 = o0 + 1;
                int4 wa = sW3[o0 * 2], wb = sW3[o0 * 2 + 1];
                int4 wc = sW3[o1 * 2], wd = sW3[o1 * 2 + 1];
                int a0 = sb3[o0], a1 = sb3[o1];
                a0 = dp4a_(q2[0], wa.x, a0); a0 = dp4a_(q2[1], wa.y, a0);
                a0 = dp4a_(q2[2], wa.z, a0); a0 = dp4a_(q2[3], wa.w, a0);
                a0 = dp4a_(q2[4], wb.x, a0); a0 = dp4a_(q2[5], wb.y, a0);
                a0 = dp4a_(q2[6], wb.z, a0); a0 = dp4a_(q2[7], wb.w, a0);
                a1 = dp4a_(q2[0], wc.x, a1); a1 = dp4a_(q2[1], wc.y, a1);
                a1 = dp4a_(q2[2], wc.z, a1); a1 = dp4a_(q2[3], wc.w, a1);
                a1 = dp4a_(q2[4], wd.x, a1); a1 = dp4a_(q2[5], wd.y, a1);
                a1 = dp4a_(q2[6], wd.z, a1); a1 = dp4a_(q2[7], wd.w, a1);
                m = fmaxf(m, __fmul_rn((float)a0, sbsf3[o0]));
                m = fmaxf(m, __fmul_rn((float)a1, sbsf3[o1]));
                w[j] = ((unsigned)a0 & 0xFFFFu) | ((unsigned)a1 << 16);
            }
            g_a3[(size_t)g * ROWS_CAP + row] = make_uint4(w[0], w[1], w[2], w[3]);
        }
    }
    warp_fmax_atomic(m, &g_hmax3);
}

// ---- K4b: sf3, cmb3, layer-4 bias quant -----------------------------------
__global__ void k4b_fin(const float* __restrict__ b4) {
    __shared__ float s_sf, s_inv;
    int t = threadIdx.x;  // 32 threads
    if (t == 0) {
        float sf = __fdiv_rn(fmaxf(__uint_as_float(g_hmax3), 1e-8f), 31.0f);
        g_sf3 = sf;
        s_sf = sf;
        s_inv = __fdiv_rn(1.0f, sf);
    }
    __syncthreads();
    g_cmb3[t] = __fmul_rn(g_bsf3[t], s_inv);
    if (t < 5) {
        float bsf = __fmul_rn(g_wsc4[t], s_sf);
        g_bsf4[t] = bsf;
        g_bint4[t] = iclamp((int)rintf(__fdiv_rn(b4[t], bsf)), -32, 31);
    }
}

// ---- K5: acc3 -> q3 -> L4, softmax, store ---------------------------------
__global__ __launch_bounds__(256, 2) void k5_out(float* __restrict__ out,
                                                 int rows, int nt) {
    __shared__ int4 sW4[10];
    __shared__ int sb4[8];
    __shared__ float2 scf3[32];
    __shared__ float sbsf4[8], scc[1];
    int t = threadIdx.x;
    if (t < 10) sW4[t] = ((const int4*)g_W4p)[t];
    if (t < 32) scf3[t] = make_float2(g_cmb3[t], g_bsf3[t]);
    if (t < 5) { sb4[t] = g_bint4[t]; sbsf4[t] = g_bsf4[t]; }
    if (t == 0) scc[0] = g_sf3;
    __syncthreads();
    float sf3 = scc[0];

#pragma unroll 1
    for (int row = blockIdx.x * 256 + t; row < rows; row += nt) {
        int q3[8];
#pragma unroll
        for (int c = 0; c < 4; c++) {
            uint4 v = g_a3[(size_t)c * ROWS_CAP + row];
            q3[c * 2 + 0] = quant4_i16(v.x, v.y, c * 8 + 0, scf3, sf3);
            q3[c * 2 + 1] = quant4_i16(v.z, v.w, c * 8 + 4, scf3, sf3);
        }
        float logit[5];
#pragma unroll
        for (int c = 0; c < 5; c++) {
            int4 wa = sW4[c * 2], wb = sW4[c * 2 + 1];
            int acc = sb4[c];
            acc = dp4a_(q3[0], wa.x, acc); acc = dp4a_(q3[1], wa.y, acc);
            acc = dp4a_(q3[2], wa.z, acc); acc = dp4a_(q3[3], wa.w, acc);
            acc = dp4a_(q3[4], wb.x, acc); acc = dp4a_(q3[5], wb.y, acc);
            acc = dp4a_(q3[6], wb.z, acc); acc = dp4a_(q3[7], wb.w, acc);
            logit[c] = __fmul_rn((float)acc, sbsf4[c]);
        }
        float mm = logit[0];
#pragma unroll
        for (int c = 1; c < 5; c++) mm = fmaxf(mm, logit[c]);
        float e[5], s = 0.f;
#pragma unroll
        for (int c = 0; c < 5; c++) { e[c] = __expf(logit[c] - mm); s += e[c]; }
        float rs = __frcp_rn(s);
        float* po = out + (size_t)row * 5;
#pragma unroll
        for (int c = 0; c < 5; c++) po[c] = e[c] * rs;
    }
}

// ---- launcher --------------------------------------------------------------
extern "C" void kernel_launch(void* const* d_in, const int* in_sizes, int n_in,
                              void* d_out, int out_size) {
    const float* x  = (const float*)d_in[0];
    const float* W1 = (const float*)d_in[1];
    const float* b1 = (const float*)d_in[2];
    const float* W2 = (const float*)d_in[3];
    const float* b2 = (const float*)d_in[4];
    const float* W3 = (const float*)d_in[5];
    const float* b3 = (const float*)d_in[6];
    const float* W4 = (const float*)d_in[7];
    const float* b4 = (const float*)d_in[8];
    float* out = (float*)d_out;

    int rows = in_sizes[0] / 16;
    if (rows > ROWS_CAP) rows = ROWS_CAP;

    int grid = (rows + 255) / 256;
    if (grid > 2368) grid = 2368;  // 148 SMs * 16 blocks
    int nt = grid * 256;

    k0_init<<<1, 256>>>(W1, W2, W3, W4);
    k1_absmax<<<1024, 256>>>(x, rows * 4);
    k1b_fin<<<1, 64>>>(b1);
    k2_l1<<<grid, 256>>>(x, rows, nt);
    k2b_fin<<<1, 64>>>(b2);
    k3_l2<<<grid, 256>>>(rows, nt);
    k3b_fin<<<1, 32>>>(b3);
    k4_l3<<<grid, 256>>>(rows, nt);
    k4b_fin<<<1, 32>>>(b4);
    k5_out<<<grid, 256>>>(out, rows, nt);
    (void)n_in; (void)out_size;
}

// round 12
// speedup vs baseline: 1.0351x; 1.0351x over previous
#include <cuda_runtime.h>
#include <cstdint>

// ---------------------------------------------------------------------------
// QThreeLayer: 6-bit quantized MLP 16 -> 64 -> 32 -> 32 -> 5, softmax.
// dp4a integer emulation, each layer computed exactly once.
// Round 9: magic-number rounding (no FRND/F2I), PRMT packing, I2F.S16 half
// converts. Exact-boundary fallback kept -> bit-identical results.
// ---------------------------------------------------------------------------

#define ROWS_CAP (1 << 20)

__device__ unsigned int g_xmax;
__device__ unsigned int g_hmax1, g_hmax2, g_hmax3;  // float-as-uint, >= 0

__device__ int g_W1p[64 * 4];
__device__ int g_W2p[32 * 16];
__device__ int g_W3p[32 * 8];
__device__ int g_W4p[8 * 8];
__device__ float g_wsc1[64], g_wsc2[32], g_wsc3[32], g_wsc4[5];

__device__ float g_sf0, g_inv0;
__device__ float g_sf1, g_sf2, g_sf3;
__device__ float g_bsf1[64], g_bsf2[32], g_bsf3[32], g_bsf4[5];
__device__ float g_cmb1[64], g_cmb2[32], g_cmb3[32];
__device__ int g_bint1[64], g_bint2[32], g_bint3[32], g_bint4[5];

// inter-phase accumulators, TRANSPOSED: element [c * ROWS_CAP + row]
__device__ uint4 g_a1[8 * ROWS_CAP];  // L1 accs int16 pairs
__device__ uint4 g_a2[8 * ROWS_CAP];  // L2 accs int32
__device__ uint4 g_a3[4 * ROWS_CAP];  // L3 accs int16 pairs

// ---- helpers ---------------------------------------------------------------
__device__ __forceinline__ int dp4a_(int a, int b, int c) {
    int d;
    asm("dp4a.s32.s32 %0, %1, %2, %3;" : "=r"(d) : "r"(a), "r"(b), "r"(c));
    return d;
}
__device__ __forceinline__ int iclamp(int v, int lo, int hi) {
    return v < lo ? lo : (v > hi ? hi : v);
}
// pack 4 low bytes via PRMT
__device__ __forceinline__ int pack4i(int a, int b, int c, int d) {
    return (int)__byte_perm(__byte_perm((unsigned)a, (unsigned)b, 0x0040u),
                            __byte_perm((unsigned)c, (unsigned)d, 0x0040u), 0x5410u);
}
// pack two int accs' low halves via PRMT
__device__ __forceinline__ unsigned packh2(int a0, int a1) {
    return __byte_perm((unsigned)a0, (unsigned)a1, 0x5410u);
}
// packed s16 pair -> two floats (I2F.S16 with half selectors)
__device__ __forceinline__ void i16x2_to_f(unsigned u, float& x, float& y) {
    short lo, hi;
    asm("mov.b32 {%0, %1}, %2;" : "=h"(lo), "=h"(hi) : "r"(u));
    asm("cvt.rn.f32.s16 %0, %1;" : "=f"(x) : "h"(lo));
    asm("cvt.rn.f32.s16 %0, %1;" : "=f"(y) : "h"(hi));
}

#define RMAGICF 12582912.0f
#define RMAGICI 0x4B400000

// signed quant round(t/s), clip [-32,31]; magic fast path + exact fallback
__device__ __forceinline__ int fquant(float t, float inv, float s) {
    float u = t * inv;
    float f = u + RMAGICF;
    int q = __float_as_int(f) - RMAGICI;
    float qf = f - RMAGICF;
    if (fabsf(u - qf) > 0.49998f) {
        float qa = rintf(__fdiv_rn(t, s));
        q = (int)qa;
    }
    return iclamp(q, -32, 31);
}

// quantize relu(acc*bsf)/sf; cb.x = bsf/sf, cb.y = bsf; result [0,31]
__device__ __forceinline__ int fquant_pos2(float accf, float2 cb, float sf) {
    float v = fmaxf(accf * cb.x, 0.f);
    float f = v + RMAGICF;
    int q = __float_as_int(f) - RMAGICI;
    float qf = f - RMAGICF;
    if (fabsf(v - qf) > 0.49998f) {
        float h = fmaxf(__fmul_rn(accf, cb.y), 0.f);
        q = (int)rintf(__fdiv_rn(h, sf));
    }
    return q > 31 ? 31 : q;
}

// quantize 4 int16-acc channels (two packed uints) into one int8x4 word
__device__ __forceinline__ int quant4_i16(unsigned u0, unsigned u1, int ob,
                                          const float2* scf, float sf) {
    float f0, f1, f2, f3;
    i16x2_to_f(u0, f0, f1);
    i16x2_to_f(u1, f2, f3);
    int a = fquant_pos2(f0, scf[ob + 0], sf);
    int b = fquant_pos2(f1, scf[ob + 1], sf);
    int c = fquant_pos2(f2, scf[ob + 2], sf);
    int d = fquant_pos2(f3, scf[ob + 3], sf);
    return pack4i(a, b, c, d);
}

__device__ __forceinline__ void warp_fmax_atomic(float m, unsigned* dst) {
#pragma unroll
    for (int s = 16; s; s >>= 1) m = fmaxf(m, __shfl_xor_sync(0xffffffffu, m, s));
    if ((threadIdx.x & 31) == 0) atomicMax(dst, __float_as_uint(m));
}

// ---- K0: reset reductions + quantize weights ------------------------------
__global__ void k0_init(const float* __restrict__ W1, const float* __restrict__ W2,
                        const float* __restrict__ W3, const float* __restrict__ W4) {
    int t = threadIdx.x;
    if (t == 0) { g_xmax = 0u; g_hmax1 = 0u; g_hmax2 = 0u; g_hmax3 = 0u; }
    if (t < 24) g_W4p[40 + t] = 0;

    if (t < 64) {
        const float* w = W1 + t * 16;
        float m = 0.f;
#pragma unroll
        for (int i = 0; i < 16; i++) m = fmaxf(m, fabsf(w[i]));
        float sc = __fdiv_rn(fmaxf(m, 1e-8f), 31.0f);
        g_wsc1[t] = sc;
#pragma unroll
        for (int k = 0; k < 4; k++) {
            int a = iclamp((int)rintf(__fdiv_rn(w[4 * k + 0], sc)), -32, 31);
            int b = iclamp((int)rintf(__fdiv_rn(w[4 * k + 1], sc)), -32, 31);
            int c = iclamp((int)rintf(__fdiv_rn(w[4 * k + 2], sc)), -32, 31);
            int d = iclamp((int)rintf(__fdiv_rn(w[4 * k + 3], sc)), -32, 31);
            g_W1p[t * 4 + k] = pack4i(a, b, c, d);
        }
    } else if (t < 96) {
        int o = t - 64;
        const float* w = W2 + o * 64;
        float m = 0.f;
#pragma unroll
        for (int i = 0; i < 64; i++) m = fmaxf(m, fabsf(w[i]));
        float sc = __fdiv_rn(fmaxf(m, 1e-8f), 31.0f);
        g_wsc2[o] = sc;
#pragma unroll
        for (int k = 0; k < 16; k++) {
            int a = iclamp((int)rintf(__fdiv_rn(w[4 * k + 0], sc)), -32, 31);
            int b = iclamp((int)rintf(__fdiv_rn(w[4 * k + 1], sc)), -32, 31);
            int c = iclamp((int)rintf(__fdiv_rn(w[4 * k + 2], sc)), -32, 31);
            int d = iclamp((int)rintf(__fdiv_rn(w[4 * k + 3], sc)), -32, 31);
            g_W2p[o * 16 + k] = pack4i(a, b, c, d);
        }
    } else if (t < 128) {
        int o = t - 96;
        const float* w = W3 + o * 32;
        float m = 0.f;
#pragma unroll
        for (int i = 0; i < 32; i++) m = fmaxf(m, fabsf(w[i]));
        float sc = __fdiv_rn(fmaxf(m, 1e-8f), 31.0f);
        g_wsc3[o] = sc;
#pragma unroll
        for (int k = 0; k < 8; k++) {
            int a = iclamp((int)rintf(__fdiv_rn(w[4 * k + 0], sc)), -32, 31);
            int b = iclamp((int)rintf(__fdiv_rn(w[4 * k + 1], sc)), -32, 31);
            int c = iclamp((int)rintf(__fdiv_rn(w[4 * k + 2], sc)), -32, 31);
            int d = iclamp((int)rintf(__fdiv_rn(w[4 * k + 3], sc)), -32, 31);
            g_W3p[o * 8 + k] = pack4i(a, b, c, d);
        }
    } else if (t < 133) {
        int o = t - 128;
        const float* w = W4 + o * 32;
        float m = 0.f;
#pragma unroll
        for (int i = 0; i < 32; i++) m = fmaxf(m, fabsf(w[i]));
        float sc = __fdiv_rn(fmaxf(m, 1e-8f), 31.0f);
        g_wsc4[o] = sc;
#pragma unroll
        for (int k = 0; k < 8; k++) {
            int a = iclamp((int)rintf(__fdiv_rn(w[4 * k + 0], sc)), -32, 31);
            int b = iclamp((int)rintf(__fdiv_rn(w[4 * k + 1], sc)), -32, 31);
            int c = iclamp((int)rintf(__fdiv_rn(w[4 * k + 2], sc)), -32, 31);
            int d = iclamp((int)rintf(__fdiv_rn(w[4 * k + 3], sc)), -32, 31);
            g_W4p[o * 8 + k] = pack4i(a, b, c, d);
        }
    }
}

// ---- K1: global max|x| -----------------------------------------------------
__global__ void k1_absmax(const float* __restrict__ x, int n4) {
    const float4* x4 = (const float4*)x;
    int i = blockIdx.x * blockDim.x + threadIdx.x;
    int stride = gridDim.x * blockDim.x;
    float m = 0.f;
    for (; i < n4; i += stride) {
        float4 v = x4[i];
        m = fmaxf(m, fmaxf(fmaxf(fabsf(v.x), fabsf(v.y)), fmaxf(fabsf(v.z), fabsf(v.w))));
    }
    warp_fmax_atomic(m, &g_xmax);
}

// ---- K1b: sf0, layer-1 bias quant -----------------------------------------
__global__ void k1b_fin(const float* __restrict__ b1) {
    __shared__ float ssf;
    int t = threadIdx.x;
    if (t == 0) {
        float sf = __fdiv_rn(fmaxf(__uint_as_float(g_xmax), 1e-8f), 31.0f);
        g_sf0 = sf;
        g_inv0 = __fdiv_rn(1.0f, sf);
        ssf = sf;
    }
    __syncthreads();
    if (t < 64) {
        float bsf = __fmul_rn(g_wsc1[t], ssf);
        g_bsf1[t] = bsf;
        g_bint1[t] = iclamp((int)rintf(__fdiv_rn(b1[t], bsf)), -32, 31);
    }
}

// ---- K2: x -> q0 (regs) -> L1, store acc1 i16 (transposed), h-max ---------
__global__ __launch_bounds__(256, 3) void k2_l1(const float* __restrict__ x,
                                                int rows, int nt) {
    __shared__ int4 sW[64];
    __shared__ int sb[64];
    __shared__ float sbsf[64], sc0[2];
    int t = threadIdx.x;
    if (t < 64) {
        sW[t] = ((const int4*)g_W1p)[t];
        sb[t] = g_bint1[t];
        sbsf[t] = g_bsf1[t];
    }
    if (t == 0) { sc0[0] = g_inv0; sc0[1] = g_sf0; }
    __syncthreads();
    float inv0 = sc0[0], sf0 = sc0[1];
    float m = 0.f;

    const float4* x4 = (const float4*)x;
#pragma unroll 1
    for (int row = blockIdx.x * 256 + t; row < rows; row += nt) {
        int qa[4];
#pragma unroll
        for (int j = 0; j < 4; j++) {
            float4 v = x4[(size_t)row * 4 + j];
            qa[j] = pack4i(fquant(v.x, inv0, sf0), fquant(v.y, inv0, sf0),
                           fquant(v.z, inv0, sf0), fquant(v.w, inv0, sf0));
        }
#pragma unroll
        for (int g = 0; g < 8; g++) {
            unsigned w[4];
#pragma unroll
            for (int j = 0; j < 4; j++) {
                int o0 = g * 8 + 2 * j, o1 = o0 + 1;
                int4 w0 = sW[o0], w1 = sW[o1];
                int a0 = sb[o0], a1 = sb[o1];
                a0 = dp4a_(qa[0], w0.x, a0); a0 = dp4a_(qa[1], w0.y, a0);
                a0 = dp4a_(qa[2], w0.z, a0); a0 = dp4a_(qa[3], w0.w, a0);
                a1 = dp4a_(qa[0], w1.x, a1); a1 = dp4a_(qa[1], w1.y, a1);
                a1 = dp4a_(qa[2], w1.z, a1); a1 = dp4a_(qa[3], w1.w, a1);
                m = fmaxf(m, __fmul_rn((float)a0, sbsf[o0]));
                m = fmaxf(m, __fmul_rn((float)a1, sbsf[o1]));
                w[j] = packh2(a0, a1);
            }
            g_a1[(size_t)g * ROWS_CAP + row] = make_uint4(w[0], w[1], w[2], w[3]);
        }
    }
    warp_fmax_atomic(m, &g_hmax1);
}

// ---- K2b: sf1, cmb1, layer-2 bias quant -----------------------------------
__global__ void k2b_fin(const float* __restrict__ b2) {
    __shared__ float s_sf, s_inv;
    int t = threadIdx.x;  // 64 threads
    if (t == 0) {
        float sf = __fdiv_rn(fmaxf(__uint_as_float(g_hmax1), 1e-8f), 31.0f);
        g_sf1 = sf;
        s_sf = sf;
        s_inv = __fdiv_rn(1.0f, sf);
    }
    __syncthreads();
    g_cmb1[t] = __fmul_rn(g_bsf1[t], s_inv);
    if (t < 32) {
        float bsf = __fmul_rn(g_wsc2[t], s_sf);
        g_bsf2[t] = bsf;
        g_bint2[t] = iclamp((int)rintf(__fdiv_rn(b2[t], bsf)), -32, 31);
    }
}

// ---- K3: acc1 -> q1 -> L2, store acc2 i32 (transposed), h-max -------------
__global__ __launch_bounds__(256, 2) void k3_l2(int rows, int nt) {
    __shared__ int4 sW2[128];
    __shared__ int sb2[32];
    __shared__ float2 scf1[64];
    __shared__ float sbsf2[32], scc[1];
    int t = threadIdx.x;
    if (t < 128) sW2[t] = ((const int4*)g_W2p)[t];
    if (t < 64) scf1[t] = make_float2(g_cmb1[t], g_bsf1[t]);
    if (t < 32) { sb2[t] = g_bint2[t]; sbsf2[t] = g_bsf2[t]; }
    if (t == 0) scc[0] = g_sf1;
    __syncthreads();
    float sf1 = scc[0];
    float m = 0.f;

#pragma unroll 1
    for (int row = blockIdx.x * 256 + t; row < rows; row += nt) {
        int q1[16];
#pragma unroll
        for (int c = 0; c < 8; c++) {
            uint4 v = g_a1[(size_t)c * ROWS_CAP + row];
            q1[c * 2 + 0] = quant4_i16(v.x, v.y, c * 8 + 0, scf1, sf1);
            q1[c * 2 + 1] = quant4_i16(v.z, v.w, c * 8 + 4, scf1, sf1);
        }
#pragma unroll
        for (int g = 0; g < 8; g++) {
            int w[4];
#pragma unroll
            for (int j = 0; j < 4; j++) {
                int o = g * 4 + j;
                int acc = sb2[o];
#pragma unroll
                for (int kk = 0; kk < 4; kk++) {
                    int4 wv = sW2[o * 4 + kk];
                    acc = dp4a_(q1[kk * 4 + 0], wv.x, acc);
                    acc = dp4a_(q1[kk * 4 + 1], wv.y, acc);
                    acc = dp4a_(q1[kk * 4 + 2], wv.z, acc);
                    acc = dp4a_(q1[kk * 4 + 3], wv.w, acc);
                }
                m = fmaxf(m, __fmul_rn((float)acc, sbsf2[o]));
                w[j] = acc;
            }
            g_a2[(size_t)g * ROWS_CAP + row] =
                make_uint4((unsigned)w[0], (unsigned)w[1], (unsigned)w[2], (unsigned)w[3]);
        }
    }
    warp_fmax_atomic(m, &g_hmax2);
}

// ---- K3b: sf2, cmb2, layer-3 bias quant -----------------------------------
__global__ void k3b_fin(const float* __restrict__ b3) {
    __shared__ float s_sf, s_inv;
    int t = threadIdx.x;  // 32 threads
    if (t == 0) {
        float sf = __fdiv_rn(fmaxf(__uint_as_float(g_hmax2), 1e-8f), 31.0f);
        g_sf2 = sf;
        s_sf = sf;
        s_inv = __fdiv_rn(1.0f, sf);
    }
    __syncthreads();
    g_cmb2[t] = __fmul_rn(g_bsf2[t], s_inv);
    {
        float bsf = __fmul_rn(g_wsc3[t], s_sf);
        g_bsf3[t] = bsf;
        g_bint3[t] = iclamp((int)rintf(__fdiv_rn(b3[t], bsf)), -32, 31);
    }
}

// ---- K4: acc2 -> q2 -> L3, store acc3 i16 (transposed), h-max -------------
__global__ __launch_bounds__(256, 2) void k4_l3(int rows, int nt) {
    __shared__ int4 sW3[64];
    __shared__ int sb3[32];
    __shared__ float2 scf2[32];
    __shared__ float sbsf3[32], scc[1];
    int t = threadIdx.x;
    if (t < 64) sW3[t] = ((const int4*)g_W3p)[t];
    if (t < 32) {
        scf2[t] = make_float2(g_cmb2[t], g_bsf2[t]);
        sb3[t] = g_bint3[t];
        sbsf3[t] = g_bsf3[t];
    }
    if (t == 0) scc[0] = g_sf2;
    __syncthreads();
    float sf2 = scc[0];
    float m = 0.f;

#pragma unroll 1
    for (int row = blockIdx.x * 256 + t; row < rows; row += nt) {
        int q2[8];
#pragma unroll
        for (int c = 0; c < 8; c++) {
            uint4 v = g_a2[(size_t)c * ROWS_CAP + row];
            int ob = c * 4;
            q2[c] = pack4i(
                fquant_pos2((float)(int)v.x, scf2[ob + 0], sf2),
                fquant_pos2((float)(int)v.y, scf2[ob + 1], sf2),
                fquant_pos2((float)(int)v.z, scf2[ob + 2], sf2),
                fquant_pos2((float)(int)v.w, scf2[ob + 3], sf2));
        }
#pragma unroll
        for (int g = 0; g < 4; g++) {
            unsigned w[4];
#pragma unroll
            for (int j = 0; j < 4; j++) {
                int o0 = g * 8 + 2 * j, o1 = o0 + 1;
                int4 wa = sW3[o0 * 2], wb = sW3[o0 * 2 + 1];
                int4 wc = sW3[o1 * 2], wd = sW3[o1 * 2 + 1];
                int a0 = sb3[o0], a1 = sb3[o1];
                a0 = dp4a_(q2[0], wa.x, a0); a0 = dp4a_(q2[1], wa.y, a0);
                a0 = dp4a_(q2[2], wa.z, a0); a0 = dp4a_(q2[3], wa.w, a0);
                a0 = dp4a_(q2[4], wb.x, a0); a0 = dp4a_(q2[5], wb.y, a0);
                a0 = dp4a_(q2[6], wb.z, a0); a0 = dp4a_(q2[7], wb.w, a0);
                a1 = dp4a_(q2[0], wc.x, a1); a1 = dp4a_(q2[1], wc.y, a1);
                a1 = dp4a_(q2[2], wc.z, a1); a1 = dp4a_(q2[3], wc.w, a1);
                a1 = dp4a_(q2[4], wd.x, a1); a1 = dp4a_(q2[5], wd.y, a1);
                a1 = dp4a_(q2[6], wd.z, a1); a1 = dp4a_(q2[7], wd.w, a1);
                m = fmaxf(m, __fmul_rn((float)a0, sbsf3[o0]));
                m = fmaxf(m, __fmul_rn((float)a1, sbsf3[o1]));
                w[j] = packh2(a0, a1);
            }
            g_a3[(size_t)g * ROWS_CAP + row] = make_uint4(w[0], w[1], w[2], w[3]);
        }
    }
    warp_fmax_atomic(m, &g_hmax3);
}

// ---- K4b: sf3, cmb3, layer-4 bias quant -----------------------------------
__global__ void k4b_fin(const float* __restrict__ b4) {
    __shared__ float s_sf, s_inv;
    int t = threadIdx.x;  // 32 threads
    if (t == 0) {
        float sf = __fdiv_rn(fmaxf(__uint_as_float(g_hmax3), 1e-8f), 31.0f);
        g_sf3 = sf;
        s_sf = sf;
        s_inv = __fdiv_rn(1.0f, sf);
    }
    __syncthreads();
    g_cmb3[t] = __fmul_rn(g_bsf3[t], s_inv);
    if (t < 5) {
        float bsf = __fmul_rn(g_wsc4[t], s_sf);
        g_bsf4[t] = bsf;
        g_bint4[t] = iclamp((int)rintf(__fdiv_rn(b4[t], bsf)), -32, 31);
    }
}

// ---- K5: acc3 -> q3 -> L4, softmax, store ---------------------------------
__global__ __launch_bounds__(256, 3) void k5_out(float* __restrict__ out,
                                                 int rows, int nt) {
    __shared__ int4 sW4[10];
    __shared__ int sb4[8];
    __shared__ float2 scf3[32];
    __shared__ float sbsf4[8], scc[1];
    int t = threadIdx.x;
    if (t < 10) sW4[t] = ((const int4*)g_W4p)[t];
    if (t < 32) scf3[t] = make_float2(g_cmb3[t], g_bsf3[t]);
    if (t < 5) { sb4[t] = g_bint4[t]; sbsf4[t] = g_bsf4[t]; }
    if (t == 0) scc[0] = g_sf3;
    __syncthreads();
    float sf3 = scc[0];

#pragma unroll 1
    for (int row = blockIdx.x * 256 + t; row < rows; row += nt) {
        int q3[8];
#pragma unroll
        for (int c = 0; c < 4; c++) {
            uint4 v = g_a3[(size_t)c * ROWS_CAP + row];
            q3[c * 2 + 0] = quant4_i16(v.x, v.y, c * 8 + 0, scf3, sf3);
            q3[c * 2 + 1] = quant4_i16(v.z, v.w, c * 8 + 4, scf3, sf3);
        }
        float logit[5];
#pragma unroll
        for (int c = 0; c < 5; c++) {
            int4 wa = sW4[c * 2], wb = sW4[c * 2 + 1];
            int acc = sb4[c];
            acc = dp4a_(q3[0], wa.x, acc); acc = dp4a_(q3[1], wa.y, acc);
            acc = dp4a_(q3[2], wa.z, acc); acc = dp4a_(q3[3], wa.w, acc);
            acc = dp4a_(q3[4], wb.x, acc); acc = dp4a_(q3[5], wb.y, acc);
            acc = dp4a_(q3[6], wb.z, acc); acc = dp4a_(q3[7], wb.w, acc);
            logit[c] = __fmul_rn((float)acc, sbsf4[c]);
        }
        float mm = logit[0];
#pragma unroll
        for (int c = 1; c < 5; c++) mm = fmaxf(mm, logit[c]);
        float e[5], s = 0.f;
#pragma unroll
        for (int c = 0; c < 5; c++) { e[c] = __expf(logit[c] - mm); s += e[c]; }
        float rs = __frcp_rn(s);
        float* po = out + (size_t)row * 5;
#pragma unroll
        for (int c = 0; c < 5; c++) po[c] = e[c] * rs;
    }
}

// ---- launcher --------------------------------------------------------------
extern "C" void kernel_launch(void* const* d_in, const int* in_sizes, int n_in,
                              void* d_out, int out_size) {
    const float* x  = (const float*)d_in[0];
    const float* W1 = (const float*)d_in[1];
    const float* b1 = (const float*)d_in[2];
    const float* W2 = (const float*)d_in[3];
    const float* b2 = (const float*)d_in[4];
    const float* W3 = (const float*)d_in[5];
    const float* b3 = (const float*)d_in[6];
    const float* W4 = (const float*)d_in[7];
    const float* b4 = (const float*)d_in[8];
    float* out = (float*)d_out;

    int rows = in_sizes[0] / 16;
    if (rows > ROWS_CAP) rows = ROWS_CAP;

    int grid = (rows + 255) / 256;
    if (grid > 2368) grid = 2368;  // 148 SMs * 16 blocks
    int nt = grid * 256;

    k0_init<<<1, 256>>>(W1, W2, W3, W4);
    k1_absmax<<<2048, 256>>>(x, rows * 4);
    k1b_fin<<<1, 64>>>(b1);
    k2_l1<<<grid, 256>>>(x, rows, nt);
    k2b_fin<<<1, 64>>>(b2);
    k3_l2<<<grid, 256>>>(rows, nt);
    k3b_fin<<<1, 32>>>(b3);
    k4_l3<<<grid, 256>>>(rows, nt);
    k4b_fin<<<1, 32>>>(b4);
    k5_out<<<grid, 256>>>(out, rows, nt);
    (void)n_in; (void)out_size;
}

// round 14
// speedup vs baseline: 1.1117x; 1.0740x over previous
#include <cuda_runtime.h>
#include <cstdint>

// ---------------------------------------------------------------------------
// QThreeLayer: 6-bit quantized MLP 16 -> 64 -> 32 -> 32 -> 5, softmax.
// dp4a integer emulation, each layer computed exactly once.
// Round 14: R13 (row-major accs + cheap quant + staged k5 output) with the
// smem staging buffer 16B-aligned (float4 flush path caused the R13 trap).
// ---------------------------------------------------------------------------

#define ROWS_CAP (1 << 20)

__device__ unsigned int g_xmax;
__device__ unsigned int g_hmax1, g_hmax2, g_hmax3;  // float-as-uint, >= 0

__device__ int g_W1p[64 * 4];
__device__ int g_W2p[32 * 16];
__device__ int g_W3p[32 * 8];
__device__ int g_W4p[8 * 8];
__device__ float g_wsc1[64], g_wsc2[32], g_wsc3[32], g_wsc4[5];

__device__ float g_sf0, g_inv0;
__device__ float g_sf1, g_sf2, g_sf3;
__device__ float g_bsf1[64], g_bsf2[32], g_bsf3[32], g_bsf4[5];
__device__ float g_cmb1[64], g_cmb2[32], g_cmb3[32];
__device__ int g_bint1[64], g_bint2[32], g_bint3[32], g_bint4[5];

// inter-phase accumulators, ROW-MAJOR: element [row * C + c]
__device__ uint4 g_a1[ROWS_CAP * 8];  // L1 accs int16 pairs (128 B/row)
__device__ uint4 g_a2[ROWS_CAP * 8];  // L2 accs int32      (128 B/row)
__device__ uint4 g_a3[ROWS_CAP * 4];  // L3 accs int16 pairs ( 64 B/row)

// ---- helpers ---------------------------------------------------------------
__device__ __forceinline__ int dp4a_(int a, int b, int c) {
    int d;
    asm("dp4a.s32.s32 %0, %1, %2, %3;" : "=r"(d) : "r"(a), "r"(b), "r"(c));
    return d;
}
__device__ __forceinline__ int iclamp(int v, int lo, int hi) {
    return v < lo ? lo : (v > hi ? hi : v);
}
// pack 4 low bytes via PRMT
__device__ __forceinline__ int pack4i(int a, int b, int c, int d) {
    return (int)__byte_perm(__byte_perm((unsigned)a, (unsigned)b, 0x0040u),
                            __byte_perm((unsigned)c, (unsigned)d, 0x0040u), 0x5410u);
}
// pack two int accs' low halves via PRMT
__device__ __forceinline__ unsigned packh2(int a0, int a1) {
    return __byte_perm((unsigned)a0, (unsigned)a1, 0x5410u);
}
// packed s16 pair -> two floats (I2F.S16 with half selectors)
__device__ __forceinline__ void i16x2_to_f(unsigned u, float& x, float& y) {
    short lo, hi;
    asm("mov.b32 {%0, %1}, %2;" : "=h"(lo), "=h"(hi) : "r"(u));
    asm("cvt.rn.f32.s16 %0, %1;" : "=f"(x) : "h"(lo));
    asm("cvt.rn.f32.s16 %0, %1;" : "=f"(y) : "h"(hi));
}

#define RMAGICF 12582912.0f
#define RMAGICI 0x4B400000

// signed quant round(t/s), clip [-32,31]; magic fast path + exact fallback
__device__ __forceinline__ int fquant(float t, float inv, float s) {
    float u = t * inv;
    float f = u + RMAGICF;
    int q = __float_as_int(f) - RMAGICI;
    float qf = f - RMAGICF;
    if (fabsf(u - qf) > 0.49998f) {
        float qa = rintf(__fdiv_rn(t, s));
        q = (int)qa;
    }
    return iclamp(q, -32, 31);
}

// quantize relu(acc*bsf)/sf; cb.x = bsf/sf, cb.y = bsf; result [0,31]
__device__ __forceinline__ int fquant_pos2(float accf, float2 cb, float sf) {
    float v = fmaxf(accf * cb.x, 0.f);
    float f = v + RMAGICF;
    int q = __float_as_int(f) - RMAGICI;
    float qf = f - RMAGICF;
    if (fabsf(v - qf) > 0.49998f) {
        float h = fmaxf(__fmul_rn(accf, cb.y), 0.f);
        q = (int)rintf(__fdiv_rn(h, sf));
    }
    return q > 31 ? 31 : q;
}

// quantize 4 int16-acc channels (two packed uints) into one int8x4 word
__device__ __forceinline__ int quant4_i16(unsigned u0, unsigned u1, int ob,
                                          const float2* scf, float sf) {
    float f0, f1, f2, f3;
    i16x2_to_f(u0, f0, f1);
    i16x2_to_f(u1, f2, f3);
    int a = fquant_pos2(f0, scf[ob + 0], sf);
    int b = fquant_pos2(f1, scf[ob + 1], sf);
    int c = fquant_pos2(f2, scf[ob + 2], sf);
    int d = fquant_pos2(f3, scf[ob + 3], sf);
    return pack4i(a, b, c, d);
}

__device__ __forceinline__ void warp_fmax_atomic(float m, unsigned* dst) {
#pragma unroll
    for (int s = 16; s; s >>= 1) m = fmaxf(m, __shfl_xor_sync(0xffffffffu, m, s));
    if ((threadIdx.x & 31) == 0) atomicMax(dst, __float_as_uint(m));
}

// ---- K0: reset reductions + quantize weights ------------------------------
__global__ void k0_init(const float* __restrict__ W1, const float* __restrict__ W2,
                        const float* __restrict__ W3, const float* __restrict__ W4) {
    int t = threadIdx.x;
    if (t == 0) { g_xmax = 0u; g_hmax1 = 0u; g_hmax2 = 0u; g_hmax3 = 0u; }
    if (t < 24) g_W4p[40 + t] = 0;

    if (t < 64) {
        const float* w = W1 + t * 16;
        float m = 0.f;
#pragma unroll
        for (int i = 0; i < 16; i++) m = fmaxf(m, fabsf(w[i]));
        float sc = __fdiv_rn(fmaxf(m, 1e-8f), 31.0f);
        g_wsc1[t] = sc;
#pragma unroll
        for (int k = 0; k < 4; k++) {
            int a = iclamp((int)rintf(__fdiv_rn(w[4 * k + 0], sc)), -32, 31);
            int b = iclamp((int)rintf(__fdiv_rn(w[4 * k + 1], sc)), -32, 31);
            int c = iclamp((int)rintf(__fdiv_rn(w[4 * k + 2], sc)), -32, 31);
            int d = iclamp((int)rintf(__fdiv_rn(w[4 * k + 3], sc)), -32, 31);
            g_W1p[t * 4 + k] = pack4i(a, b, c, d);
        }
    } else if (t < 96) {
        int o = t - 64;
        const float* w = W2 + o * 64;
        float m = 0.f;
#pragma unroll
        for (int i = 0; i < 64; i++) m = fmaxf(m, fabsf(w[i]));
        float sc = __fdiv_rn(fmaxf(m, 1e-8f), 31.0f);
        g_wsc2[o] = sc;
#pragma unroll
        for (int k = 0; k < 16; k++) {
            int a = iclamp((int)rintf(__fdiv_rn(w[4 * k + 0], sc)), -32, 31);
            int b = iclamp((int)rintf(__fdiv_rn(w[4 * k + 1], sc)), -32, 31);
            int c = iclamp((int)rintf(__fdiv_rn(w[4 * k + 2], sc)), -32, 31);
            int d = iclamp((int)rintf(__fdiv_rn(w[4 * k + 3], sc)), -32, 31);
            g_W2p[o * 16 + k] = pack4i(a, b, c, d);
        }
    } else if (t < 128) {
        int o = t - 96;
        const float* w = W3 + o * 32;
        float m = 0.f;
#pragma unroll
        for (int i = 0; i < 32; i++) m = fmaxf(m, fabsf(w[i]));
        float sc = __fdiv_rn(fmaxf(m, 1e-8f), 31.0f);
        g_wsc3[o] = sc;
#pragma unroll
        for (int k = 0; k < 8; k++) {
            int a = iclamp((int)rintf(__fdiv_rn(w[4 * k + 0], sc)), -32, 31);
            int b = iclamp((int)rintf(__fdiv_rn(w[4 * k + 1], sc)), -32, 31);
            int c = iclamp((int)rintf(__fdiv_rn(w[4 * k + 2], sc)), -32, 31);
            int d = iclamp((int)rintf(__fdiv_rn(w[4 * k + 3], sc)), -32, 31);
            g_W3p[o * 8 + k] = pack4i(a, b, c, d);
        }
    } else if (t < 133) {
        int o = t - 128;
        const float* w = W4 + o * 32;
        float m = 0.f;
#pragma unroll
        for (int i = 0; i < 32; i++) m = fmaxf(m, fabsf(w[i]));
        float sc = __fdiv_rn(fmaxf(m, 1e-8f), 31.0f);
        g_wsc4[o] = sc;
#pragma unroll
        for (int k = 0; k < 8; k++) {
            int a = iclamp((int)rintf(__fdiv_rn(w[4 * k + 0], sc)), -32, 31);
            int b = iclamp((int)rintf(__fdiv_rn(w[4 * k + 1], sc)), -32, 31);
            int c = iclamp((int)rintf(__fdiv_rn(w[4 * k + 2], sc)), -32, 31);
            int d = iclamp((int)rintf(__fdiv_rn(w[4 * k + 3], sc)), -32, 31);
            g_W4p[o * 8 + k] = pack4i(a, b, c, d);
        }
    }
}

// ---- K1: global max|x| -----------------------------------------------------
__global__ void k1_absmax(const float* __restrict__ x, int n4) {
    const float4* x4 = (const float4*)x;
    int i = blockIdx.x * blockDim.x + threadIdx.x;
    int stride = gridDim.x * blockDim.x;
    float m = 0.f;
    for (; i < n4; i += stride) {
        float4 v = x4[i];
        m = fmaxf(m, fmaxf(fmaxf(fabsf(v.x), fabsf(v.y)), fmaxf(fabsf(v.z), fabsf(v.w))));
    }
    warp_fmax_atomic(m, &g_xmax);
}

// ---- K1b: sf0, layer-1 bias quant -----------------------------------------
__global__ void k1b_fin(const float* __restrict__ b1) {
    __shared__ float ssf;
    int t = threadIdx.x;
    if (t == 0) {
        float sf = __fdiv_rn(fmaxf(__uint_as_float(g_xmax), 1e-8f), 31.0f);
        g_sf0 = sf;
        g_inv0 = __fdiv_rn(1.0f, sf);
        ssf = sf;
    }
    __syncthreads();
    if (t < 64) {
        float bsf = __fmul_rn(g_wsc1[t], ssf);
        g_bsf1[t] = bsf;
        g_bint1[t] = iclamp((int)rintf(__fdiv_rn(b1[t], bsf)), -32, 31);
    }
}

// ---- K2: x -> q0 (regs) -> L1, store acc1 i16 (row-major), h-max ----------
__global__ __launch_bounds__(256, 2) void k2_l1(const float* __restrict__ x,
                                                int rows, int nt) {
    __shared__ int4 sW[64];
    __shared__ int sb[64];
    __shared__ float sbsf[64], sc0[2];
    int t = threadIdx.x;
    if (t < 64) {
        sW[t] = ((const int4*)g_W1p)[t];
        sb[t] = g_bint1[t];
        sbsf[t] = g_bsf1[t];
    }
    if (t == 0) { sc0[0] = g_inv0; sc0[1] = g_sf0; }
    __syncthreads();
    float inv0 = sc0[0], sf0 = sc0[1];
    float m = 0.f;

    const float4* x4 = (const float4*)x;
#pragma unroll 1
    for (int row = blockIdx.x * 256 + t; row < rows; row += nt) {
        int qa[4];
#pragma unroll
        for (int j = 0; j < 4; j++) {
            float4 v = x4[(size_t)row * 4 + j];
            qa[j] = pack4i(fquant(v.x, inv0, sf0), fquant(v.y, inv0, sf0),
                           fquant(v.z, inv0, sf0), fquant(v.w, inv0, sf0));
        }
        uint4* prow = g_a1 + (size_t)row * 8;
#pragma unroll
        for (int g = 0; g < 8; g++) {
            unsigned w[4];
#pragma unroll
            for (int j = 0; j < 4; j++) {
                int o0 = g * 8 + 2 * j, o1 = o0 + 1;
                int4 w0 = sW[o0], w1 = sW[o1];
                int a0 = sb[o0], a1 = sb[o1];
                a0 = dp4a_(qa[0], w0.x, a0); a0 = dp4a_(qa[1], w0.y, a0);
                a0 = dp4a_(qa[2], w0.z, a0); a0 = dp4a_(qa[3], w0.w, a0);
                a1 = dp4a_(qa[0], w1.x, a1); a1 = dp4a_(qa[1], w1.y, a1);
                a1 = dp4a_(qa[2], w1.z, a1); a1 = dp4a_(qa[3], w1.w, a1);
                m = fmaxf(m, __fmul_rn((float)a0, sbsf[o0]));
                m = fmaxf(m, __fmul_rn((float)a1, sbsf[o1]));
                w[j] = packh2(a0, a1);
            }
            prow[g] = make_uint4(w[0], w[1], w[2], w[3]);
        }
    }
    warp_fmax_atomic(m, &g_hmax1);
}

// ---- K2b: sf1, cmb1, layer-2 bias quant -----------------------------------
__global__ void k2b_fin(const float* __restrict__ b2) {
    __shared__ float s_sf, s_inv;
    int t = threadIdx.x;  // 64 threads
    if (t == 0) {
        float sf = __fdiv_rn(fmaxf(__uint_as_float(g_hmax1), 1e-8f), 31.0f);
        g_sf1 = sf;
        s_sf = sf;
        s_inv = __fdiv_rn(1.0f, sf);
    }
    __syncthreads();
    g_cmb1[t] = __fmul_rn(g_bsf1[t], s_inv);
    if (t < 32) {
        float bsf = __fmul_rn(g_wsc2[t], s_sf);
        g_bsf2[t] = bsf;
        g_bint2[t] = iclamp((int)rintf(__fdiv_rn(b2[t], bsf)), -32, 31);
    }
}

// ---- K3: acc1 -> q1 -> L2, store acc2 i32 (row-major), h-max --------------
__global__ __launch_bounds__(256, 2) void k3_l2(int rows, int nt) {
    __shared__ int4 sW2[128];
    __shared__ int sb2[32];
    __shared__ float2 scf1[64];
    __shared__ float sbsf2[32], scc[1];
    int t = threadIdx.x;
    if (t < 128) sW2[t] = ((const int4*)g_W2p)[t];
    if (t < 64) scf1[t] = make_float2(g_cmb1[t], g_bsf1[t]);
    if (t < 32) { sb2[t] = g_bint2[t]; sbsf2[t] = g_bsf2[t]; }
    if (t == 0) scc[0] = g_sf1;
    __syncthreads();
    float sf1 = scc[0];
    float m = 0.f;

#pragma unroll 1
    for (int row = blockIdx.x * 256 + t; row < rows; row += nt) {
        const uint4* pa = g_a1 + (size_t)row * 8;
        int q1[16];
#pragma unroll
        for (int c = 0; c < 8; c++) {
            uint4 v = pa[c];
            q1[c * 2 + 0] = quant4_i16(v.x, v.y, c * 8 + 0, scf1, sf1);
            q1[c * 2 + 1] = quant4_i16(v.z, v.w, c * 8 + 4, scf1, sf1);
        }
        uint4* orow = g_a2 + (size_t)row * 8;
#pragma unroll
        for (int g = 0; g < 8; g++) {
            int w[4];
#pragma unroll
            for (int j = 0; j < 4; j++) {
                int o = g * 4 + j;
                int acc = sb2[o];
#pragma unroll
                for (int kk = 0; kk < 4; kk++) {
                    int4 wv = sW2[o * 4 + kk];
                    acc = dp4a_(q1[kk * 4 + 0], wv.x, acc);
                    acc = dp4a_(q1[kk * 4 + 1], wv.y, acc);
                    acc = dp4a_(q1[kk * 4 + 2], wv.z, acc);
                    acc = dp4a_(q1[kk * 4 + 3], wv.w, acc);
                }
                m = fmaxf(m, __fmul_rn((float)acc, sbsf2[o]));
                w[j] = acc;
            }
            orow[g] = make_uint4((unsigned)w[0], (unsigned)w[1],
                                 (unsigned)w[2], (unsigned)w[3]);
        }
    }
    warp_fmax_atomic(m, &g_hmax2);
}

// ---- K3b: sf2, cmb2, layer-3 bias quant -----------------------------------
__global__ void k3b_fin(const float* __restrict__ b3) {
    __shared__ float s_sf, s_inv;
    int t = threadIdx.x;  // 32 threads
    if (t == 0) {
        float sf = __fdiv_rn(fmaxf(__uint_as_float(g_hmax2), 1e-8f), 31.0f);
        g_sf2 = sf;
        s_sf = sf;
        s_inv = __fdiv_rn(1.0f, sf);
    }
    __syncthreads();
    g_cmb2[t] = __fmul_rn(g_bsf2[t], s_inv);
    {
        float bsf = __fmul_rn(g_wsc3[t], s_sf);
        g_bsf3[t] = bsf;
        g_bint3[t] = iclamp((int)rintf(__fdiv_rn(b3[t], bsf)), -32, 31);
    }
}

// ---- K4: acc2 -> q2 -> L3, store acc3 i16 (row-major), h-max --------------
__global__ __launch_bounds__(256, 2) void k4_l3(int rows, int nt) {
    __shared__ int4 sW3[64];
    __shared__ int sb3[32];
    __shared__ float2 scf2[32];
    __shared__ float sbsf3[32], scc[1];
    int t = threadIdx.x;
    if (t < 64) sW3[t] = ((const int4*)g_W3p)[t];
    if (t < 32) {
        scf2[t] = make_float2(g_cmb2[t], g_bsf2[t]);
        sb3[t] = g_bint3[t];
        sbsf3[t] = g_bsf3[t];
    }
    if (t == 0) scc[0] = g_sf2;
    __syncthreads();
    float sf2 = scc[0];
    float m = 0.f;

#pragma unroll 1
    for (int row = blockIdx.x * 256 + t; row < rows; row += nt) {
        const uint4* pa = g_a2 + (size_t)row * 8;
        int q2[8];
#pragma unroll
        for (int c = 0; c < 8; c++) {
            uint4 v = pa[c];
            int ob = c * 4;
            q2[c] = pack4i(
                fquant_pos2((float)(int)v.x, scf2[ob + 0], sf2),
                fquant_pos2((float)(int)v.y, scf2[ob + 1], sf2),
                fquant_pos2((float)(int)v.z, scf2[ob + 2], sf2),
                fquant_pos2((float)(int)v.w, scf2[ob + 3], sf2));
        }
        uint4* orow = g_a3 + (size_t)row * 4;
#pragma unroll
        for (int g = 0; g < 4; g++) {
            unsigned w[4];
#pragma unroll
            for (int j = 0; j < 4; j++) {
                int o0 = g * 8 + 2 * j, o1 = o0 + 1;
                int4 wa = sW3[o0 * 2], wb = sW3[o0 * 2 + 1];
                int4 wc = sW3[o1 * 2], wd = sW3[o1 * 2 + 1];
                int a0 = sb3[o0], a1 = sb3[o1];
                a0 = dp4a_(q2[0], wa.x, a0); a0 = dp4a_(q2[1], wa.y, a0);
                a0 = dp4a_(q2[2], wa.z, a0); a0 = dp4a_(q2[3], wa.w, a0);
                a0 = dp4a_(q2[4], wb.x, a0); a0 = dp4a_(q2[5], wb.y, a0);
                a0 = dp4a_(q2[6], wb.z, a0); a0 = dp4a_(q2[7], wb.w, a0);
                a1 = dp4a_(q2[0], wc.x, a1); a1 = dp4a_(q2[1], wc.y, a1);
                a1 = dp4a_(q2[2], wc.z, a1); a1 = dp4a_(q2[3], wc.w, a1);
                a1 = dp4a_(q2[4], wd.x, a1); a1 = dp4a_(q2[5], wd.y, a1);
                a1 = dp4a_(q2[6], wd.z, a1); a1 = dp4a_(q2[7], wd.w, a1);
                m = fmaxf(m, __fmul_rn((float)a0, sbsf3[o0]));
                m = fmaxf(m, __fmul_rn((float)a1, sbsf3[o1]));
                w[j] = packh2(a0, a1);
            }
            orow[g] = make_uint4(w[0], w[1], w[2], w[3]);
        }
    }
    warp_fmax_atomic(m, &g_hmax3);
}

// ---- K4b: sf3, cmb3, layer-4 bias quant -----------------------------------
__global__ void k4b_fin(const float* __restrict__ b4) {
    __shared__ float s_sf, s_inv;
    int t = threadIdx.x;  // 32 threads
    if (t == 0) {
        float sf = __fdiv_rn(fmaxf(__uint_as_float(g_hmax3), 1e-8f), 31.0f);
        g_sf3 = sf;
        s_sf = sf;
        s_inv = __fdiv_rn(1.0f, sf);
    }
    __syncthreads();
    g_cmb3[t] = __fmul_rn(g_bsf3[t], s_inv);
    if (t < 5) {
        float bsf = __fmul_rn(g_wsc4[t], s_sf);
        g_bsf4[t] = bsf;
        g_bint4[t] = iclamp((int)rintf(__fdiv_rn(b4[t], bsf)), -32, 31);
    }
}

// ---- K5: acc3 -> q3 -> L4, softmax, smem-staged coalesced store -----------
__global__ __launch_bounds__(256, 3) void k5_out(float* __restrict__ out,
                                                 int rows, int nt) {
    __shared__ int4 sW4[10];
    __shared__ int sb4[8];
    __shared__ float2 scf3[32];
    __shared__ float sbsf4[8], scc[1];
    __shared__ __align__(16) float sobuf[1280];  // 256 rows x 5 probs (16B-aligned for float4 flush)
    int t = threadIdx.x;
    if (t < 10) sW4[t] = ((const int4*)g_W4p)[t];
    if (t < 32) scf3[t] = make_float2(g_cmb3[t], g_bsf3[t]);
    if (t < 5) { sb4[t] = g_bint4[t]; sbsf4[t] = g_bsf4[t]; }
    if (t == 0) scc[0] = g_sf3;
    __syncthreads();
    float sf3 = scc[0];

#pragma unroll 1
    for (int base = blockIdx.x * 256; base < rows; base += nt) {
        int row = base + t;
        if (row < rows) {
            const uint4* pa = g_a3 + (size_t)row * 4;
            int q3[8];
#pragma unroll
            for (int c = 0; c < 4; c++) {
                uint4 v = pa[c];
                q3[c * 2 + 0] = quant4_i16(v.x, v.y, c * 8 + 0, scf3, sf3);
                q3[c * 2 + 1] = quant4_i16(v.z, v.w, c * 8 + 4, scf3, sf3);
            }
            float logit[5];
#pragma unroll
            for (int c = 0; c < 5; c++) {
                int4 wa = sW4[c * 2], wb = sW4[c * 2 + 1];
                int acc = sb4[c];
                acc = dp4a_(q3[0], wa.x, acc); acc = dp4a_(q3[1], wa.y, acc);
                acc = dp4a_(q3[2], wa.z, acc); acc = dp4a_(q3[3], wa.w, acc);
                acc = dp4a_(q3[4], wb.x, acc); acc = dp4a_(q3[5], wb.y, acc);
                acc = dp4a_(q3[6], wb.z, acc); acc = dp4a_(q3[7], wb.w, acc);
                logit[c] = __fmul_rn((float)acc, sbsf4[c]);
            }
            float mm = logit[0];
#pragma unroll
            for (int c = 1; c < 5; c++) mm = fmaxf(mm, logit[c]);
            float e[5], s = 0.f;
#pragma unroll
            for (int c = 0; c < 5; c++) { e[c] = __expf(logit[c] - mm); s += e[c]; }
            float rs = __frcp_rn(s);
#pragma unroll
            for (int c = 0; c < 5; c++) sobuf[t * 5 + c] = e[c] * rs;  // stride 5: bank-conflict-free
        }
        __syncthreads();
        int n = rows - base;
        if (n > 256) n = 256;
        float* gbase = out + (size_t)base * 5;
        if (n == 256) {
            float4* g4 = (float4*)gbase;
            const float4* s4 = (const float4*)sobuf;
#pragma unroll
            for (int i = t; i < 320; i += 256) g4[i] = s4[i];
        } else {
            int n5 = n * 5;
            for (int i = t; i < n5; i += 256) gbase[i] = sobuf[i];
        }
        __syncthreads();
    }
}

// ---- launcher --------------------------------------------------------------
extern "C" void kernel_launch(void* const* d_in, const int* in_sizes, int n_in,
                              void* d_out, int out_size) {
    const float* x  = (const float*)d_in[0];
    const float* W1 = (const float*)d_in[1];
    const float* b1 = (const float*)d_in[2];
    const float* W2 = (const float*)d_in[3];
    const float* b2 = (const float*)d_in[4];
    const float* W3 = (const float*)d_in[5];
    const float* b3 = (const float*)d_in[6];
    const float* W4 = (const float*)d_in[7];
    const float* b4 = (const float*)d_in[8];
    float* out = (float*)d_out;

    int rows = in_sizes[0] / 16;
    if (rows > ROWS_CAP) rows = ROWS_CAP;

    int grid = (rows + 255) / 256;
    if (grid > 2368) grid = 2368;  // 148 SMs * 16 blocks
    int nt = grid * 256;

    k0_init<<<1, 256>>>(W1, W2, W3, W4);
    k1_absmax<<<2048, 256>>>(x, rows * 4);
    k1b_fin<<<1, 64>>>(b1);
    k2_l1<<<grid, 256>>>(x, rows, nt);
    k2b_fin<<<1, 64>>>(b2);
    k3_l2<<<grid, 256>>>(rows, nt);
    k3b_fin<<<1, 32>>>(b3);
    k4_l3<<<grid, 256>>>(rows, nt);
    k4b_fin<<<1, 32>>>(b4);
    k5_out<<<grid, 256>>>(out, rows, nt);
    (void)n_in; (void)out_size;
}

// round 15
// speedup vs baseline: 1.2503x; 1.1247x over previous
#include <cuda_runtime.h>
#include <cstdint>

// ---------------------------------------------------------------------------
// QThreeLayer: 6-bit quantized MLP 16 -> 64 -> 32 -> 32 -> 5, softmax.
// dp4a integer emulation, each layer computed exactly once.
// Round 15: row-major global accumulators, but k2/k3/k4 stores staged through
// padded per-warp smem tiles and flushed coalesced (8wf/row -> ~1.3wf/row).
// ---------------------------------------------------------------------------

#define ROWS_CAP (1 << 20)

__device__ unsigned int g_xmax;
__device__ unsigned int g_hmax1, g_hmax2, g_hmax3;  // float-as-uint, >= 0

__device__ int g_W1p[64 * 4];
__device__ int g_W2p[32 * 16];
__device__ int g_W3p[32 * 8];
__device__ int g_W4p[8 * 8];
__device__ float g_wsc1[64], g_wsc2[32], g_wsc3[32], g_wsc4[5];

__device__ float g_sf0, g_inv0;
__device__ float g_sf1, g_sf2, g_sf3;
__device__ float g_bsf1[64], g_bsf2[32], g_bsf3[32], g_bsf4[5];
__device__ float g_cmb1[64], g_cmb2[32], g_cmb3[32];
__device__ int g_bint1[64], g_bint2[32], g_bint3[32], g_bint4[5];

// inter-phase accumulators, ROW-MAJOR: element [row * C + c]
__device__ uint4 g_a1[ROWS_CAP * 8];  // L1 accs int16 pairs (128 B/row)
__device__ uint4 g_a2[ROWS_CAP * 8];  // L2 accs int32      (128 B/row)
__device__ uint4 g_a3[ROWS_CAP * 4];  // L3 accs int16 pairs ( 64 B/row)

// ---- helpers ---------------------------------------------------------------
__device__ __forceinline__ int dp4a_(int a, int b, int c) {
    int d;
    asm("dp4a.s32.s32 %0, %1, %2, %3;" : "=r"(d) : "r"(a), "r"(b), "r"(c));
    return d;
}
__device__ __forceinline__ int iclamp(int v, int lo, int hi) {
    return v < lo ? lo : (v > hi ? hi : v);
}
// pack 4 low bytes via PRMT
__device__ __forceinline__ int pack4i(int a, int b, int c, int d) {
    return (int)__byte_perm(__byte_perm((unsigned)a, (unsigned)b, 0x0040u),
                            __byte_perm((unsigned)c, (unsigned)d, 0x0040u), 0x5410u);
}
// pack two int accs' low halves via PRMT
__device__ __forceinline__ unsigned packh2(int a0, int a1) {
    return __byte_perm((unsigned)a0, (unsigned)a1, 0x5410u);
}
// packed s16 pair -> two floats (I2F.S16 with half selectors)
__device__ __forceinline__ void i16x2_to_f(unsigned u, float& x, float& y) {
    short lo, hi;
    asm("mov.b32 {%0, %1}, %2;" : "=h"(lo), "=h"(hi) : "r"(u));
    asm("cvt.rn.f32.s16 %0, %1;" : "=f"(x) : "h"(lo));
    asm("cvt.rn.f32.s16 %0, %1;" : "=f"(y) : "h"(hi));
}

#define RMAGICF 12582912.0f
#define RMAGICI 0x4B400000

// signed quant round(t/s), clip [-32,31]; magic fast path + exact fallback
__device__ __forceinline__ int fquant(float t, float inv, float s) {
    float u = t * inv;
    float f = u + RMAGICF;
    int q = __float_as_int(f) - RMAGICI;
    float qf = f - RMAGICF;
    if (fabsf(u - qf) > 0.49998f) {
        float qa = rintf(__fdiv_rn(t, s));
        q = (int)qa;
    }
    return iclamp(q, -32, 31);
}

// quantize relu(acc*bsf)/sf; cb.x = bsf/sf, cb.y = bsf; result [0,31]
__device__ __forceinline__ int fquant_pos2(float accf, float2 cb, float sf) {
    float v = fmaxf(accf * cb.x, 0.f);
    float f = v + RMAGICF;
    int q = __float_as_int(f) - RMAGICI;
    float qf = f - RMAGICF;
    if (fabsf(v - qf) > 0.49998f) {
        float h = fmaxf(__fmul_rn(accf, cb.y), 0.f);
        q = (int)rintf(__fdiv_rn(h, sf));
    }
    return q > 31 ? 31 : q;
}

// quantize 4 int16-acc channels (two packed uints) into one int8x4 word
__device__ __forceinline__ int quant4_i16(unsigned u0, unsigned u1, int ob,
                                          const float2* scf, float sf) {
    float f0, f1, f2, f3;
    i16x2_to_f(u0, f0, f1);
    i16x2_to_f(u1, f2, f3);
    int a = fquant_pos2(f0, scf[ob + 0], sf);
    int b = fquant_pos2(f1, scf[ob + 1], sf);
    int c = fquant_pos2(f2, scf[ob + 2], sf);
    int d = fquant_pos2(f3, scf[ob + 3], sf);
    return pack4i(a, b, c, d);
}

__device__ __forceinline__ void warp_fmax_atomic(float m, unsigned* dst) {
#pragma unroll
    for (int s = 16; s; s >>= 1) m = fmaxf(m, __shfl_xor_sync(0xffffffffu, m, s));
    if ((threadIdx.x & 31) == 0) atomicMax(dst, __float_as_uint(m));
}

// ---- K0: reset reductions + quantize weights ------------------------------
__global__ void k0_init(const float* __restrict__ W1, const float* __restrict__ W2,
                        const float* __restrict__ W3, const float* __restrict__ W4) {
    int t = threadIdx.x;
    if (t == 0) { g_xmax = 0u; g_hmax1 = 0u; g_hmax2 = 0u; g_hmax3 = 0u; }
    if (t < 24) g_W4p[40 + t] = 0;

    if (t < 64) {
        const float* w = W1 + t * 16;
        float m = 0.f;
#pragma unroll
        for (int i = 0; i < 16; i++) m = fmaxf(m, fabsf(w[i]));
        float sc = __fdiv_rn(fmaxf(m, 1e-8f), 31.0f);
        g_wsc1[t] = sc;
#pragma unroll
        for (int k = 0; k < 4; k++) {
            int a = iclamp((int)rintf(__fdiv_rn(w[4 * k + 0], sc)), -32, 31);
            int b = iclamp((int)rintf(__fdiv_rn(w[4 * k + 1], sc)), -32, 31);
            int c = iclamp((int)rintf(__fdiv_rn(w[4 * k + 2], sc)), -32, 31);
            int d = iclamp((int)rintf(__fdiv_rn(w[4 * k + 3], sc)), -32, 31);
            g_W1p[t * 4 + k] = pack4i(a, b, c, d);
        }
    } else if (t < 96) {
        int o = t - 64;
        const float* w = W2 + o * 64;
        float m = 0.f;
#pragma unroll
        for (int i = 0; i < 64; i++) m = fmaxf(m, fabsf(w[i]));
        float sc = __fdiv_rn(fmaxf(m, 1e-8f), 31.0f);
        g_wsc2[o] = sc;
#pragma unroll
        for (int k = 0; k < 16; k++) {
            int a = iclamp((int)rintf(__fdiv_rn(w[4 * k + 0], sc)), -32, 31);
            int b = iclamp((int)rintf(__fdiv_rn(w[4 * k + 1], sc)), -32, 31);
            int c = iclamp((int)rintf(__fdiv_rn(w[4 * k + 2], sc)), -32, 31);
            int d = iclamp((int)rintf(__fdiv_rn(w[4 * k + 3], sc)), -32, 31);
            g_W2p[o * 16 + k] = pack4i(a, b, c, d);
        }
    } else if (t < 128) {
        int o = t - 96;
        const float* w = W3 + o * 32;
        float m = 0.f;
#pragma unroll
        for (int i = 0; i < 32; i++) m = fmaxf(m, fabsf(w[i]));
        float sc = __fdiv_rn(fmaxf(m, 1e-8f), 31.0f);
        g_wsc3[o] = sc;
#pragma unroll
        for (int k = 0; k < 8; k++) {
            int a = iclamp((int)rintf(__fdiv_rn(w[4 * k + 0], sc)), -32, 31);
            int b = iclamp((int)rintf(__fdiv_rn(w[4 * k + 1], sc)), -32, 31);
            int c = iclamp((int)rintf(__fdiv_rn(w[4 * k + 2], sc)), -32, 31);
            int d = iclamp((int)rintf(__fdiv_rn(w[4 * k + 3], sc)), -32, 31);
            g_W3p[o * 8 + k] = pack4i(a, b, c, d);
        }
    } else if (t < 133) {
        int o = t - 128;
        const float* w = W4 + o * 32;
        float m = 0.f;
#pragma unroll
        for (int i = 0; i < 32; i++) m = fmaxf(m, fabsf(w[i]));
        float sc = __fdiv_rn(fmaxf(m, 1e-8f), 31.0f);
        g_wsc4[o] = sc;
#pragma unroll
        for (int k = 0; k < 8; k++) {
            int a = iclamp((int)rintf(__fdiv_rn(w[4 * k + 0], sc)), -32, 31);
            int b = iclamp((int)rintf(__fdiv_rn(w[4 * k + 1], sc)), -32, 31);
            int c = iclamp((int)rintf(__fdiv_rn(w[4 * k + 2], sc)), -32, 31);
            int d = iclamp((int)rintf(__fdiv_rn(w[4 * k + 3], sc)), -32, 31);
            g_W4p[o * 8 + k] = pack4i(a, b, c, d);
        }
    }
}

// ---- K1: global max|x| -----------------------------------------------------
__global__ void k1_absmax(const float* __restrict__ x, int n4) {
    const float4* x4 = (const float4*)x;
    int i = blockIdx.x * blockDim.x + threadIdx.x;
    int stride = gridDim.x * blockDim.x;
    float m = 0.f;
    for (; i < n4; i += stride) {
        float4 v = x4[i];
        m = fmaxf(m, fmaxf(fmaxf(fabsf(v.x), fabsf(v.y)), fmaxf(fabsf(v.z), fabsf(v.w))));
    }
    warp_fmax_atomic(m, &g_xmax);
}

// ---- K1b: sf0, layer-1 bias quant -----------------------------------------
__global__ void k1b_fin(const float* __restrict__ b1) {
    __shared__ float ssf;
    int t = threadIdx.x;
    if (t == 0) {
        float sf = __fdiv_rn(fmaxf(__uint_as_float(g_xmax), 1e-8f), 31.0f);
        g_sf0 = sf;
        g_inv0 = __fdiv_rn(1.0f, sf);
        ssf = sf;
    }
    __syncthreads();
    if (t < 64) {
        float bsf = __fmul_rn(g_wsc1[t], ssf);
        g_bsf1[t] = bsf;
        g_bint1[t] = iclamp((int)rintf(__fdiv_rn(b1[t], bsf)), -32, 31);
    }
}

// warp-cooperative coalesced flush of a per-warp staged tile.
// NCHUNK uint4 per row, SSTRIDE uint4 smem row stride, 32 rows per warp.
template <int NCHUNK, int SSTRIDE>
__device__ __forceinline__ void flush_tile(uint4* gdst /* row-major, NCHUNK per row */,
                                           const uint4* swarp, int lane, int nvalid) {
    if (nvalid == 32) {
#pragma unroll
        for (int it = 0; it < NCHUNK; it++) {
            int linear = it * 32 + lane;
            int lr = linear / NCHUNK, gg = linear % NCHUNK;
            gdst[linear] = swarp[lr * SSTRIDE + gg];
        }
    } else {
        int lim = nvalid * NCHUNK;
        for (int it = 0; it < NCHUNK; it++) {
            int linear = it * 32 + lane;
            if (linear < lim) {
                int lr = linear / NCHUNK, gg = linear % NCHUNK;
                gdst[linear] = swarp[lr * SSTRIDE + gg];
            }
        }
    }
}

// ---- K2: x -> q0 (regs) -> L1, acc1 i16 staged + coalesced store, h-max ---
__global__ __launch_bounds__(256, 2) void k2_l1(const float* __restrict__ x,
                                                int rows, int nt) {
    __shared__ int4 sW[64];
    __shared__ int sb[64];
    __shared__ float sbsf[64], sc0[2];
    __shared__ __align__(16) uint4 sstage[8 * 32 * 9];  // 36,864 B
    int t = threadIdx.x;
    int wid = t >> 5, lane = t & 31;
    if (t < 64) {
        sW[t] = ((const int4*)g_W1p)[t];
        sb[t] = g_bint1[t];
        sbsf[t] = g_bsf1[t];
    }
    if (t == 0) { sc0[0] = g_inv0; sc0[1] = g_sf0; }
    __syncthreads();
    float inv0 = sc0[0], sf0 = sc0[1];
    float m = 0.f;
    uint4* swarp = sstage + wid * (32 * 9);
    uint4* smine = swarp + lane * 9;

    const float4* x4 = (const float4*)x;
#pragma unroll 1
    for (int wbase = blockIdx.x * 256 + wid * 32; wbase < rows; wbase += nt) {
        int row = wbase + lane;
        int nvalid = rows - wbase;
        if (nvalid > 32) nvalid = 32;
        if (row < rows) {
            int qa[4];
#pragma unroll
            for (int j = 0; j < 4; j++) {
                float4 v = x4[(size_t)row * 4 + j];
                qa[j] = pack4i(fquant(v.x, inv0, sf0), fquant(v.y, inv0, sf0),
                               fquant(v.z, inv0, sf0), fquant(v.w, inv0, sf0));
            }
#pragma unroll
            for (int g = 0; g < 8; g++) {
                unsigned w[4];
#pragma unroll
                for (int j = 0; j < 4; j++) {
                    int o0 = g * 8 + 2 * j, o1 = o0 + 1;
                    int4 w0 = sW[o0], w1 = sW[o1];
                    int a0 = sb[o0], a1 = sb[o1];
                    a0 = dp4a_(qa[0], w0.x, a0); a0 = dp4a_(qa[1], w0.y, a0);
                    a0 = dp4a_(qa[2], w0.z, a0); a0 = dp4a_(qa[3], w0.w, a0);
                    a1 = dp4a_(qa[0], w1.x, a1); a1 = dp4a_(qa[1], w1.y, a1);
                    a1 = dp4a_(qa[2], w1.z, a1); a1 = dp4a_(qa[3], w1.w, a1);
                    m = fmaxf(m, __fmul_rn((float)a0, sbsf[o0]));
                    m = fmaxf(m, __fmul_rn((float)a1, sbsf[o1]));
                    w[j] = packh2(a0, a1);
                }
                smine[g] = make_uint4(w[0], w[1], w[2], w[3]);
            }
        }
        __syncwarp();
        flush_tile<8, 9>(g_a1 + (size_t)wbase * 8, swarp, lane, nvalid);
        __syncwarp();
    }
    warp_fmax_atomic(m, &g_hmax1);
}

// ---- K2b: sf1, cmb1, layer-2 bias quant -----------------------------------
__global__ void k2b_fin(const float* __restrict__ b2) {
    __shared__ float s_sf, s_inv;
    int t = threadIdx.x;  // 64 threads
    if (t == 0) {
        float sf = __fdiv_rn(fmaxf(__uint_as_float(g_hmax1), 1e-8f), 31.0f);
        g_sf1 = sf;
        s_sf = sf;
        s_inv = __fdiv_rn(1.0f, sf);
    }
    __syncthreads();
    g_cmb1[t] = __fmul_rn(g_bsf1[t], s_inv);
    if (t < 32) {
        float bsf = __fmul_rn(g_wsc2[t], s_sf);
        g_bsf2[t] = bsf;
        g_bint2[t] = iclamp((int)rintf(__fdiv_rn(b2[t], bsf)), -32, 31);
    }
}

// ---- K3: acc1 -> q1 -> L2, acc2 i32 staged + coalesced store, h-max -------
__global__ __launch_bounds__(256, 2) void k3_l2(int rows, int nt) {
    __shared__ int4 sW2[128];
    __shared__ int sb2[32];
    __shared__ float2 scf1[64];
    __shared__ float sbsf2[32], scc[1];
    __shared__ __align__(16) uint4 sstage[8 * 32 * 9];  // 36,864 B
    int t = threadIdx.x;
    int wid = t >> 5, lane = t & 31;
    if (t < 128) sW2[t] = ((const int4*)g_W2p)[t];
    if (t < 64) scf1[t] = make_float2(g_cmb1[t], g_bsf1[t]);
    if (t < 32) { sb2[t] = g_bint2[t]; sbsf2[t] = g_bsf2[t]; }
    if (t == 0) scc[0] = g_sf1;
    __syncthreads();
    float sf1 = scc[0];
    float m = 0.f;
    uint4* swarp = sstage + wid * (32 * 9);
    uint4* smine = swarp + lane * 9;

#pragma unroll 1
    for (int wbase = blockIdx.x * 256 + wid * 32; wbase < rows; wbase += nt) {
        int row = wbase + lane;
        int nvalid = rows - wbase;
        if (nvalid > 32) nvalid = 32;
        if (row < rows) {
            const uint4* pa = g_a1 + (size_t)row * 8;
            int q1[16];
#pragma unroll
            for (int c = 0; c < 8; c++) {
                uint4 v = pa[c];
                q1[c * 2 + 0] = quant4_i16(v.x, v.y, c * 8 + 0, scf1, sf1);
                q1[c * 2 + 1] = quant4_i16(v.z, v.w, c * 8 + 4, scf1, sf1);
            }
#pragma unroll
            for (int g = 0; g < 8; g++) {
                int w[4];
#pragma unroll
                for (int j = 0; j < 4; j++) {
                    int o = g * 4 + j;
                    int acc = sb2[o];
#pragma unroll
                    for (int kk = 0; kk < 4; kk++) {
                        int4 wv = sW2[o * 4 + kk];
                        acc = dp4a_(q1[kk * 4 + 0], wv.x, acc);
                        acc = dp4a_(q1[kk * 4 + 1], wv.y, acc);
                        acc = dp4a_(q1[kk * 4 + 2], wv.z, acc);
                        acc = dp4a_(q1[kk * 4 + 3], wv.w, acc);
                    }
                    m = fmaxf(m, __fmul_rn((float)acc, sbsf2[o]));
                    w[j] = acc;
                }
                smine[g] = make_uint4((unsigned)w[0], (unsigned)w[1],
                                      (unsigned)w[2], (unsigned)w[3]);
            }
        }
        __syncwarp();
        flush_tile<8, 9>(g_a2 + (size_t)wbase * 8, swarp, lane, nvalid);
        __syncwarp();
    }
    warp_fmax_atomic(m, &g_hmax2);
}

// ---- K3b: sf2, cmb2, layer-3 bias quant -----------------------------------
__global__ void k3b_fin(const float* __restrict__ b3) {
    __shared__ float s_sf, s_inv;
    int t = threadIdx.x;  // 32 threads
    if (t == 0) {
        float sf = __fdiv_rn(fmaxf(__uint_as_float(g_hmax2), 1e-8f), 31.0f);
        g_sf2 = sf;
        s_sf = sf;
        s_inv = __fdiv_rn(1.0f, sf);
    }
    __syncthreads();
    g_cmb2[t] = __fmul_rn(g_bsf2[t], s_inv);
    {
        float bsf = __fmul_rn(g_wsc3[t], s_sf);
        g_bsf3[t] = bsf;
        g_bint3[t] = iclamp((int)rintf(__fdiv_rn(b3[t], bsf)), -32, 31);
    }
}

// ---- K4: acc2 -> q2 -> L3, acc3 i16 staged + coalesced store, h-max -------
__global__ __launch_bounds__(256, 2) void k4_l3(int rows, int nt) {
    __shared__ int4 sW3[64];
    __shared__ int sb3[32];
    __shared__ float2 scf2[32];
    __shared__ float sbsf3[32], scc[1];
    __shared__ __align__(16) uint4 sstage[8 * 32 * 5];  // 20,480 B
    int t = threadIdx.x;
    int wid = t >> 5, lane = t & 31;
    if (t < 64) sW3[t] = ((const int4*)g_W3p)[t];
    if (t < 32) {
        scf2[t] = make_float2(g_cmb2[t], g_bsf2[t]);
        sb3[t] = g_bint3[t];
        sbsf3[t] = g_bsf3[t];
    }
    if (t == 0) scc[0] = g_sf2;
    __syncthreads();
    float sf2 = scc[0];
    float m = 0.f;
    uint4* swarp = sstage + wid * (32 * 5);
    uint4* smine = swarp + lane * 5;

#pragma unroll 1
    for (int wbase = blockIdx.x * 256 + wid * 32; wbase < rows; wbase += nt) {
        int row = wbase + lane;
        int nvalid = rows - wbase;
        if (nvalid > 32) nvalid = 32;
        if (row < rows) {
            const uint4* pa = g_a2 + (size_t)row * 8;
            int q2[8];
#pragma unroll
            for (int c = 0; c < 8; c++) {
                uint4 v = pa[c];
                int ob = c * 4;
                q2[c] = pack4i(
                    fquant_pos2((float)(int)v.x, scf2[ob + 0], sf2),
                    fquant_pos2((float)(int)v.y, scf2[ob + 1], sf2),
                    fquant_pos2((float)(int)v.z, scf2[ob + 2], sf2),
                    fquant_pos2((float)(int)v.w, scf2[ob + 3], sf2));
            }
#pragma unroll
            for (int g = 0; g < 4; g++) {
                unsigned w[4];
#pragma unroll
                for (int j = 0; j < 4; j++) {
                    int o0 = g * 8 + 2 * j, o1 = o0 + 1;
                    int4 wa = sW3[o0 * 2], wb = sW3[o0 * 2 + 1];
                    int4 wc = sW3[o1 * 2], wd = sW3[o1 * 2 + 1];
                    int a0 = sb3[o0], a1 = sb3[o1];
                    a0 = dp4a_(q2[0], wa.x, a0); a0 = dp4a_(q2[1], wa.y, a0);
                    a0 = dp4a_(q2[2], wa.z, a0); a0 = dp4a_(q2[3], wa.w, a0);
                    a0 = dp4a_(q2[4], wb.x, a0); a0 = dp4a_(q2[5], wb.y, a0);
                    a0 = dp4a_(q2[6], wb.z, a0); a0 = dp4a_(q2[7], wb.w, a0);
                    a1 = dp4a_(q2[0], wc.x, a1); a1 = dp4a_(q2[1], wc.y, a1);
                    a1 = dp4a_(q2[2], wc.z, a1); a1 = dp4a_(q2[3], wc.w, a1);
                    a1 = dp4a_(q2[4], wd.x, a1); a1 = dp4a_(q2[5], wd.y, a1);
                    a1 = dp4a_(q2[6], wd.z, a1); a1 = dp4a_(q2[7], wd.w, a1);
                    m = fmaxf(m, __fmul_rn((float)a0, sbsf3[o0]));
                    m = fmaxf(m, __fmul_rn((float)a1, sbsf3[o1]));
                    w[j] = packh2(a0, a1);
                }
                smine[g] = make_uint4(w[0], w[1], w[2], w[3]);
            }
        }
        __syncwarp();
        flush_tile<4, 5>(g_a3 + (size_t)wbase * 4, swarp, lane, nvalid);
        __syncwarp();
    }
    warp_fmax_atomic(m, &g_hmax3);
}

// ---- K4b: sf3, cmb3, layer-4 bias quant -----------------------------------
__global__ void k4b_fin(const float* __restrict__ b4) {
    __shared__ float s_sf, s_inv;
    int t = threadIdx.x;  // 32 threads
    if (t == 0) {
        float sf = __fdiv_rn(fmaxf(__uint_as_float(g_hmax3), 1e-8f), 31.0f);
        g_sf3 = sf;
        s_sf = sf;
        s_inv = __fdiv_rn(1.0f, sf);
    }
    __syncthreads();
    g_cmb3[t] = __fmul_rn(g_bsf3[t], s_inv);
    if (t < 5) {
        float bsf = __fmul_rn(g_wsc4[t], s_sf);
        g_bsf4[t] = bsf;
        g_bint4[t] = iclamp((int)rintf(__fdiv_rn(b4[t], bsf)), -32, 31);
    }
}

// ---- K5: acc3 -> q3 -> L4, softmax, smem-staged coalesced store -----------
__global__ __launch_bounds__(256, 3) void k5_out(float* __restrict__ out,
                                                 int rows, int nt) {
    __shared__ int4 sW4[10];
    __shared__ int sb4[8];
    __shared__ float2 scf3[32];
    __shared__ float sbsf4[8], scc[1];
    __shared__ __align__(16) float sobuf[1280];  // 256 rows x 5 probs
    int t = threadIdx.x;
    if (t < 10) sW4[t] = ((const int4*)g_W4p)[t];
    if (t < 32) scf3[t] = make_float2(g_cmb3[t], g_bsf3[t]);
    if (t < 5) { sb4[t] = g_bint4[t]; sbsf4[t] = g_bsf4[t]; }
    if (t == 0) scc[0] = g_sf3;
    __syncthreads();
    float sf3 = scc[0];

#pragma unroll 1
    for (int base = blockIdx.x * 256; base < rows; base += nt) {
        int row = base + t;
        if (row < rows) {
            const uint4* pa = g_a3 + (size_t)row * 4;
            int q3[8];
#pragma unroll
            for (int c = 0; c < 4; c++) {
                uint4 v = pa[c];
                q3[c * 2 + 0] = quant4_i16(v.x, v.y, c * 8 + 0, scf3, sf3);
                q3[c * 2 + 1] = quant4_i16(v.z, v.w, c * 8 + 4, scf3, sf3);
            }
            float logit[5];
#pragma unroll
            for (int c = 0; c < 5; c++) {
                int4 wa = sW4[c * 2], wb = sW4[c * 2 + 1];
                int acc = sb4[c];
                acc = dp4a_(q3[0], wa.x, acc); acc = dp4a_(q3[1], wa.y, acc);
                acc = dp4a_(q3[2], wa.z, acc); acc = dp4a_(q3[3], wa.w, acc);
                acc = dp4a_(q3[4], wb.x, acc); acc = dp4a_(q3[5], wb.y, acc);
                acc = dp4a_(q3[6], wb.z, acc); acc = dp4a_(q3[7], wb.w, acc);
                logit[c] = __fmul_rn((float)acc, sbsf4[c]);
            }
            float mm = logit[0];
#pragma unroll
            for (int c = 1; c < 5; c++) mm = fmaxf(mm, logit[c]);
            float e[5], s = 0.f;
#pragma unroll
            for (int c = 0; c < 5; c++) { e[c] = __expf(logit[c] - mm); s += e[c]; }
            float rs = __frcp_rn(s);
#pragma unroll
            for (int c = 0; c < 5; c++) sobuf[t * 5 + c] = e[c] * rs;
        }
        __syncthreads();
        int n = rows - base;
        if (n > 256) n = 256;
        float* gbase = out + (size_t)base * 5;
        if (n == 256) {
            float4* g4 = (float4*)gbase;
            const float4* s4 = (const float4*)sobuf;
#pragma unroll
            for (int i = t; i < 320; i += 256) g4[i] = s4[i];
        } else {
            int n5 = n * 5;
            for (int i = t; i < n5; i += 256) gbase[i] = sobuf[i];
        }
        __syncthreads();
    }
}

// ---- launcher --------------------------------------------------------------
extern "C" void kernel_launch(void* const* d_in, const int* in_sizes, int n_in,
                              void* d_out, int out_size) {
    const float* x  = (const float*)d_in[0];
    const float* W1 = (const float*)d_in[1];
    const float* b1 = (const float*)d_in[2];
    const float* W2 = (const float*)d_in[3];
    const float* b2 = (const float*)d_in[4];
    const float* W3 = (const float*)d_in[5];
    const float* b3 = (const float*)d_in[6];
    const float* W4 = (const float*)d_in[7];
    const float* b4 = (const float*)d_in[8];
    float* out = (float*)d_out;

    int rows = in_sizes[0] / 16;
    if (rows > ROWS_CAP) rows = ROWS_CAP;

    int grid = (rows + 255) / 256;
    if (grid > 2368) grid = 2368;  // 148 SMs * 16 blocks
    int nt = grid * 256;

    k0_init<<<1, 256>>>(W1, W2, W3, W4);
    k1_absmax<<<2048, 256>>>(x, rows * 4);
    k1b_fin<<<1, 64>>>(b1);
    k2_l1<<<grid, 256>>>(x, rows, nt);
    k2b_fin<<<1, 64>>>(b2);
    k3_l2<<<grid, 256>>>(rows, nt);
    k3b_fin<<<1, 32>>>(b3);
    k4_l3<<<grid, 256>>>(rows, nt);
    k4b_fin<<<1, 32>>>(b4);
    k5_out<<<grid, 256>>>(out, rows, nt);
    (void)n_in; (void)out_size;
}

// round 17
// speedup vs baseline: 1.3390x; 1.0710x over previous
#include <cuda_runtime.h>
#include <cstdint>

// ---------------------------------------------------------------------------
// QThreeLayer: 6-bit quantized MLP 16 -> 64 -> 32 -> 32 -> 5, softmax.
// dp4a integer emulation, each layer computed exactly once.
// Round 16: symmetric smem staging — strided global LOADS also go through the
// per-warp tile (coalesced gather + LDS), reusing the store-staging buffer.
// ---------------------------------------------------------------------------

#define ROWS_CAP (1 << 20)

__device__ unsigned int g_xmax;
__device__ unsigned int g_hmax1, g_hmax2, g_hmax3;  // float-as-uint, >= 0

__device__ int g_W1p[64 * 4];
__device__ int g_W2p[32 * 16];
__device__ int g_W3p[32 * 8];
__device__ int g_W4p[8 * 8];
__device__ float g_wsc1[64], g_wsc2[32], g_wsc3[32], g_wsc4[5];

__device__ float g_sf0, g_inv0;
__device__ float g_sf1, g_sf2, g_sf3;
__device__ float g_bsf1[64], g_bsf2[32], g_bsf3[32], g_bsf4[5];
__device__ float g_cmb1[64], g_cmb2[32], g_cmb3[32];
__device__ int g_bint1[64], g_bint2[32], g_bint3[32], g_bint4[5];

// inter-phase accumulators, ROW-MAJOR: element [row * C + c]
__device__ uint4 g_a1[ROWS_CAP * 8];  // L1 accs int16 pairs (128 B/row)
__device__ uint4 g_a2[ROWS_CAP * 8];  // L2 accs int32      (128 B/row)
__device__ uint4 g_a3[ROWS_CAP * 4];  // L3 accs int16 pairs ( 64 B/row)

// ---- helpers ---------------------------------------------------------------
__device__ __forceinline__ int dp4a_(int a, int b, int c) {
    int d;
    asm("dp4a.s32.s32 %0, %1, %2, %3;" : "=r"(d) : "r"(a), "r"(b), "r"(c));
    return d;
}
__device__ __forceinline__ int iclamp(int v, int lo, int hi) {
    return v < lo ? lo : (v > hi ? hi : v);
}
// pack 4 low bytes via PRMT
__device__ __forceinline__ int pack4i(int a, int b, int c, int d) {
    return (int)__byte_perm(__byte_perm((unsigned)a, (unsigned)b, 0x0040u),
                            __byte_perm((unsigned)c, (unsigned)d, 0x0040u), 0x5410u);
}
// pack two int accs' low halves via PRMT
__device__ __forceinline__ unsigned packh2(int a0, int a1) {
    return __byte_perm((unsigned)a0, (unsigned)a1, 0x5410u);
}
// packed s16 pair -> two floats (I2F.S16 with half selectors)
__device__ __forceinline__ void i16x2_to_f(unsigned u, float& x, float& y) {
    short lo, hi;
    asm("mov.b32 {%0, %1}, %2;" : "=h"(lo), "=h"(hi) : "r"(u));
    asm("cvt.rn.f32.s16 %0, %1;" : "=f"(x) : "h"(lo));
    asm("cvt.rn.f32.s16 %0, %1;" : "=f"(y) : "h"(hi));
}

#define RMAGICF 12582912.0f
#define RMAGICI 0x4B400000

// signed quant round(t/s), clip [-32,31]; magic fast path + exact fallback
__device__ __forceinline__ int fquant(float t, float inv, float s) {
    float u = t * inv;
    float f = u + RMAGICF;
    int q = __float_as_int(f) - RMAGICI;
    float qf = f - RMAGICF;
    if (fabsf(u - qf) > 0.49998f) {
        float qa = rintf(__fdiv_rn(t, s));
        q = (int)qa;
    }
    return iclamp(q, -32, 31);
}

// quantize relu(acc*bsf)/sf; cb.x = bsf/sf, cb.y = bsf; result [0,31]
__device__ __forceinline__ int fquant_pos2(float accf, float2 cb, float sf) {
    float v = fmaxf(accf * cb.x, 0.f);
    float f = v + RMAGICF;
    int q = __float_as_int(f) - RMAGICI;
    float qf = f - RMAGICF;
    if (fabsf(v - qf) > 0.49998f) {
        float h = fmaxf(__fmul_rn(accf, cb.y), 0.f);
        q = (int)rintf(__fdiv_rn(h, sf));
    }
    return q > 31 ? 31 : q;
}

// quantize 4 int16-acc channels (two packed uints) into one int8x4 word
__device__ __forceinline__ int quant4_i16(unsigned u0, unsigned u1, int ob,
                                          const float2* scf, float sf) {
    float f0, f1, f2, f3;
    i16x2_to_f(u0, f0, f1);
    i16x2_to_f(u1, f2, f3);
    int a = fquant_pos2(f0, scf[ob + 0], sf);
    int b = fquant_pos2(f1, scf[ob + 1], sf);
    int c = fquant_pos2(f2, scf[ob + 2], sf);
    int d = fquant_pos2(f3, scf[ob + 3], sf);
    return pack4i(a, b, c, d);
}

__device__ __forceinline__ void warp_fmax_atomic(float m, unsigned* dst) {
#pragma unroll
    for (int s = 16; s; s >>= 1) m = fmaxf(m, __shfl_xor_sync(0xffffffffu, m, s));
    if ((threadIdx.x & 31) == 0) atomicMax(dst, __float_as_uint(m));
}

// warp-cooperative coalesced flush: smem tile -> row-major global.
template <int NCHUNK, int SSTRIDE>
__device__ __forceinline__ void flush_tile(uint4* gdst, const uint4* swarp,
                                           int lane, int nvalid) {
    if (nvalid == 32) {
#pragma unroll
        for (int it = 0; it < NCHUNK; it++) {
            int linear = it * 32 + lane;
            int lr = linear / NCHUNK, gg = linear % NCHUNK;
            gdst[linear] = swarp[lr * SSTRIDE + gg];
        }
    } else {
        int lim = nvalid * NCHUNK;
        for (int it = 0; it < NCHUNK; it++) {
            int linear = it * 32 + lane;
            if (linear < lim) {
                int lr = linear / NCHUNK, gg = linear % NCHUNK;
                gdst[linear] = swarp[lr * SSTRIDE + gg];
            }
        }
    }
}

// warp-cooperative coalesced gather: row-major global -> smem tile.
template <int NCHUNK, int SSTRIDE>
__device__ __forceinline__ void load_tile(uint4* swarp, const uint4* gsrc,
                                          int lane, int nvalid) {
    if (nvalid == 32) {
#pragma unroll
        for (int it = 0; it < NCHUNK; it++) {
            int linear = it * 32 + lane;
            int lr = linear / NCHUNK, gg = linear % NCHUNK;
            swarp[lr * SSTRIDE + gg] = gsrc[linear];
        }
    } else {
        int lim = nvalid * NCHUNK;
        for (int it = 0; it < NCHUNK; it++) {
            int linear = it * 32 + lane;
            if (linear < lim) {
                int lr = linear / NCHUNK, gg = linear % NCHUNK;
                swarp[lr * SSTRIDE + gg] = gsrc[linear];
            }
        }
    }
}

// ---- K0: reset reductions + quantize weights ------------------------------
__global__ void k0_init(const float* __restrict__ W1, const float* __restrict__ W2,
                        const float* __restrict__ W3, const float* __restrict__ W4) {
    int t = threadIdx.x;
    if (t == 0) { g_xmax = 0u; g_hmax1 = 0u; g_hmax2 = 0u; g_hmax3 = 0u; }
    if (t < 24) g_W4p[40 + t] = 0;

    if (t < 64) {
        const float* w = W1 + t * 16;
        float m = 0.f;
#pragma unroll
        for (int i = 0; i < 16; i++) m = fmaxf(m, fabsf(w[i]));
        float sc = __fdiv_rn(fmaxf(m, 1e-8f), 31.0f);
        g_wsc1[t] = sc;
#pragma unroll
        for (int k = 0; k < 4; k++) {
            int a = iclamp((int)rintf(__fdiv_rn(w[4 * k + 0], sc)), -32, 31);
            int b = iclamp((int)rintf(__fdiv_rn(w[4 * k + 1], sc)), -32, 31);
            int c = iclamp((int)rintf(__fdiv_rn(w[4 * k + 2], sc)), -32, 31);
            int d = iclamp((int)rintf(__fdiv_rn(w[4 * k + 3], sc)), -32, 31);
            g_W1p[t * 4 + k] = pack4i(a, b, c, d);
        }
    } else if (t < 96) {
        int o = t - 64;
        const float* w = W2 + o * 64;
        float m = 0.f;
#pragma unroll
        for (int i = 0; i < 64; i++) m = fmaxf(m, fabsf(w[i]));
        float sc = __fdiv_rn(fmaxf(m, 1e-8f), 31.0f);
        g_wsc2[o] = sc;
#pragma unroll
        for (int k = 0; k < 16; k++) {
            int a = iclamp((int)rintf(__fdiv_rn(w[4 * k + 0], sc)), -32, 31);
            int b = iclamp((int)rintf(__fdiv_rn(w[4 * k + 1], sc)), -32, 31);
            int c = iclamp((int)rintf(__fdiv_rn(w[4 * k + 2], sc)), -32, 31);
            int d = iclamp((int)rintf(__fdiv_rn(w[4 * k + 3], sc)), -32, 31);
            g_W2p[o * 16 + k] = pack4i(a, b, c, d);
        }
    } else if (t < 128) {
        int o = t - 96;
        const float* w = W3 + o * 32;
        float m = 0.f;
#pragma unroll
        for (int i = 0; i < 32; i++) m = fmaxf(m, fabsf(w[i]));
        float sc = __fdiv_rn(fmaxf(m, 1e-8f), 31.0f);
        g_wsc3[o] = sc;
#pragma unroll
        for (int k = 0; k < 8; k++) {
            int a = iclamp((int)rintf(__fdiv_rn(w[4 * k + 0], sc)), -32, 31);
            int b = iclamp((int)rintf(__fdiv_rn(w[4 * k + 1], sc)), -32, 31);
            int c = iclamp((int)rintf(__fdiv_rn(w[4 * k + 2], sc)), -32, 31);
            int d = iclamp((int)rintf(__fdiv_rn(w[4 * k + 3], sc)), -32, 31);
            g_W3p[o * 8 + k] = pack4i(a, b, c, d);
        }
    } else if (t < 133) {
        int o = t - 128;
        const float* w = W4 + o * 32;
        float m = 0.f;
#pragma unroll
        for (int i = 0; i < 32; i++) m = fmaxf(m, fabsf(w[i]));
        float sc = __fdiv_rn(fmaxf(m, 1e-8f), 31.0f);
        g_wsc4[o] = sc;
#pragma unroll
        for (int k = 0; k < 8; k++) {
            int a = iclamp((int)rintf(__fdiv_rn(w[4 * k + 0], sc)), -32, 31);
            int b = iclamp((int)rintf(__fdiv_rn(w[4 * k + 1], sc)), -32, 31);
            int c = iclamp((int)rintf(__fdiv_rn(w[4 * k + 2], sc)), -32, 31);
            int d = iclamp((int)rintf(__fdiv_rn(w[4 * k + 3], sc)), -32, 31);
            g_W4p[o * 8 + k] = pack4i(a, b, c, d);
        }
    }
}

// ---- K1: global max|x| -----------------------------------------------------
__global__ void k1_absmax(const float* __restrict__ x, int n4) {
    const float4* x4 = (const float4*)x;
    int i = blockIdx.x * blockDim.x + threadIdx.x;
    int stride = gridDim.x * blockDim.x;
    float m = 0.f;
    for (; i < n4; i += stride) {
        float4 v = x4[i];
        m = fmaxf(m, fmaxf(fmaxf(fabsf(v.x), fabsf(v.y)), fmaxf(fabsf(v.z), fabsf(v.w))));
    }
    warp_fmax_atomic(m, &g_xmax);
}

// ---- K1b: sf0, layer-1 bias quant -----------------------------------------
__global__ void k1b_fin(const float* __restrict__ b1) {
    __shared__ float ssf;
    int t = threadIdx.x;
    if (t == 0) {
        float sf = __fdiv_rn(fmaxf(__uint_as_float(g_xmax), 1e-8f), 31.0f);
        g_sf0 = sf;
        g_inv0 = __fdiv_rn(1.0f, sf);
        ssf = sf;
    }
    __syncthreads();
    if (t < 64) {
        float bsf = __fmul_rn(g_wsc1[t], ssf);
        g_bsf1[t] = bsf;
        g_bint1[t] = iclamp((int)rintf(__fdiv_rn(b1[t], bsf)), -32, 31);
    }
}

// ---- K2: x (staged in) -> q0 -> L1 -> acc1 (staged out), h-max ------------
__global__ __launch_bounds__(256, 2) void k2_l1(const float* __restrict__ x,
                                                int rows, int nt) {
    __shared__ int4 sW[64];
    __shared__ int sb[64];
    __shared__ float sbsf[64], sc0[2];
    __shared__ __align__(16) uint4 sstage[8 * 32 * 9];  // 36,864 B
    int t = threadIdx.x;
    int wid = t >> 5, lane = t & 31;
    if (t < 64) {
        sW[t] = ((const int4*)g_W1p)[t];
        sb[t] = g_bint1[t];
        sbsf[t] = g_bsf1[t];
    }
    if (t == 0) { sc0[0] = g_inv0; sc0[1] = g_sf0; }
    __syncthreads();
    float inv0 = sc0[0], sf0 = sc0[1];
    float m = 0.f;
    uint4* swarp = sstage + wid * (32 * 9);
    uint4* smine = swarp + lane * 9;

    const uint4* x4g = (const uint4*)x;
#pragma unroll 1
    for (int wbase = blockIdx.x * 256 + wid * 32; wbase < rows; wbase += nt) {
        int nvalid = rows - wbase;
        if (nvalid > 32) nvalid = 32;
        load_tile<4, 9>(swarp, x4g + (size_t)wbase * 4, lane, nvalid);
        __syncwarp();
        if (lane < nvalid) {
            int qa[4];
#pragma unroll
            for (int j = 0; j < 4; j++) {
                uint4 u = smine[j];
                qa[j] = pack4i(fquant(__uint_as_float(u.x), inv0, sf0),
                               fquant(__uint_as_float(u.y), inv0, sf0),
                               fquant(__uint_as_float(u.z), inv0, sf0),
                               fquant(__uint_as_float(u.w), inv0, sf0));
            }
#pragma unroll
            for (int g = 0; g < 8; g++) {
                unsigned w[4];
#pragma unroll
                for (int j = 0; j < 4; j++) {
                    int o0 = g * 8 + 2 * j, o1 = o0 + 1;
                    int4 w0 = sW[o0], w1 = sW[o1];
                    int a0 = sb[o0], a1 = sb[o1];
                    a0 = dp4a_(qa[0], w0.x, a0); a0 = dp4a_(qa[1], w0.y, a0);
                    a0 = dp4a_(qa[2], w0.z, a0); a0 = dp4a_(qa[3], w0.w, a0);
                    a1 = dp4a_(qa[0], w1.x, a1); a1 = dp4a_(qa[1], w1.y, a1);
                    a1 = dp4a_(qa[2], w1.z, a1); a1 = dp4a_(qa[3], w1.w, a1);
                    m = fmaxf(m, __fmul_rn((float)a0, sbsf[o0]));
                    m = fmaxf(m, __fmul_rn((float)a1, sbsf[o1]));
                    w[j] = packh2(a0, a1);
                }
                smine[g] = make_uint4(w[0], w[1], w[2], w[3]);
            }
        }
        __syncwarp();
        flush_tile<8, 9>(g_a1 + (size_t)wbase * 8, swarp, lane, nvalid);
        __syncwarp();
    }
    warp_fmax_atomic(m, &g_hmax1);
}

// ---- K2b: sf1, cmb1, layer-2 bias quant -----------------------------------
__global__ void k2b_fin(const float* __restrict__ b2) {
    __shared__ float s_sf, s_inv;
    int t = threadIdx.x;  // 64 threads
    if (t == 0) {
        float sf = __fdiv_rn(fmaxf(__uint_as_float(g_hmax1), 1e-8f), 31.0f);
        g_sf1 = sf;
        s_sf = sf;
        s_inv = __fdiv_rn(1.0f, sf);
    }
    __syncthreads();
    g_cmb1[t] = __fmul_rn(g_bsf1[t], s_inv);
    if (t < 32) {
        float bsf = __fmul_rn(g_wsc2[t], s_sf);
        g_bsf2[t] = bsf;
        g_bint2[t] = iclamp((int)rintf(__fdiv_rn(b2[t], bsf)), -32, 31);
    }
}

// ---- K3: acc1 (staged in) -> q1 -> L2 -> acc2 (staged out), h-max ---------
__global__ __launch_bounds__(256, 2) void k3_l2(int rows, int nt) {
    __shared__ int4 sW2[128];
    __shared__ int sb2[32];
    __shared__ float2 scf1[64];
    __shared__ float sbsf2[32], scc[1];
    __shared__ __align__(16) uint4 sstage[8 * 32 * 9];  // 36,864 B
    int t = threadIdx.x;
    int wid = t >> 5, lane = t & 31;
    if (t < 128) sW2[t] = ((const int4*)g_W2p)[t];
    if (t < 64) scf1[t] = make_float2(g_cmb1[t], g_bsf1[t]);
    if (t < 32) { sb2[t] = g_bint2[t]; sbsf2[t] = g_bsf2[t]; }
    if (t == 0) scc[0] = g_sf1;
    __syncthreads();
    float sf1 = scc[0];
    float m = 0.f;
    uint4* swarp = sstage + wid * (32 * 9);
    uint4* smine = swarp + lane * 9;

#pragma unroll 1
    for (int wbase = blockIdx.x * 256 + wid * 32; wbase < rows; wbase += nt) {
        int nvalid = rows - wbase;
        if (nvalid > 32) nvalid = 32;
        load_tile<8, 9>(swarp, g_a1 + (size_t)wbase * 8, lane, nvalid);
        __syncwarp();
        if (lane < nvalid) {
            int q1[16];
#pragma unroll
            for (int c = 0; c < 8; c++) {
                uint4 v = smine[c];
                q1[c * 2 + 0] = quant4_i16(v.x, v.y, c * 8 + 0, scf1, sf1);
                q1[c * 2 + 1] = quant4_i16(v.z, v.w, c * 8 + 4, scf1, sf1);
            }
#pragma unroll
            for (int g = 0; g < 8; g++) {
                int w[4];
#pragma unroll
                for (int j = 0; j < 4; j++) {
                    int o = g * 4 + j;
                    int acc = sb2[o];
#pragma unroll
                    for (int kk = 0; kk < 4; kk++) {
                        int4 wv = sW2[o * 4 + kk];
                        acc = dp4a_(q1[kk * 4 + 0], wv.x, acc);
                        acc = dp4a_(q1[kk * 4 + 1], wv.y, acc);
                        acc = dp4a_(q1[kk * 4 + 2], wv.z, acc);
                        acc = dp4a_(q1[kk * 4 + 3], wv.w, acc);
                    }
                    m = fmaxf(m, __fmul_rn((float)acc, sbsf2[o]));
                    w[j] = acc;
                }
                smine[g] = make_uint4((unsigned)w[0], (unsigned)w[1],
                                      (unsigned)w[2], (unsigned)w[3]);
            }
        }
        __syncwarp();
        flush_tile<8, 9>(g_a2 + (size_t)wbase * 8, swarp, lane, nvalid);
        __syncwarp();
    }
    warp_fmax_atomic(m, &g_hmax2);
}

// ---- K3b: sf2, cmb2, layer-3 bias quant -----------------------------------
__global__ void k3b_fin(const float* __restrict__ b3) {
    __shared__ float s_sf, s_inv;
    int t = threadIdx.x;  // 32 threads
    if (t == 0) {
        float sf = __fdiv_rn(fmaxf(__uint_as_float(g_hmax2), 1e-8f), 31.0f);
        g_sf2 = sf;
        s_sf = sf;
        s_inv = __fdiv_rn(1.0f, sf);
    }
    __syncthreads();
    g_cmb2[t] = __fmul_rn(g_bsf2[t], s_inv);
    {
        float bsf = __fmul_rn(g_wsc3[t], s_sf);
        g_bsf3[t] = bsf;
        g_bint3[t] = iclamp((int)rintf(__fdiv_rn(b3[t], bsf)), -32, 31);
    }
}

// ---- K4: acc2 (staged in) -> q2 -> L3 -> acc3 (staged out), h-max ---------
__global__ __launch_bounds__(256, 2) void k4_l3(int rows, int nt) {
    __shared__ int4 sW3[64];
    __shared__ int sb3[32];
    __shared__ float2 scf2[32];
    __shared__ float sbsf3[32], scc[1];
    __shared__ __align__(16) uint4 sstage[8 * 32 * 9];  // 36,864 B (in 8, out 4)
    int t = threadIdx.x;
    int wid = t >> 5, lane = t & 31;
    if (t < 64) sW3[t] = ((const int4*)g_W3p)[t];
    if (t < 32) {
        scf2[t] = make_float2(g_cmb2[t], g_bsf2[t]);
        sb3[t] = g_bint3[t];
        sbsf3[t] = g_bsf3[t];
    }
    if (t == 0) scc[0] = g_sf2;
    __syncthreads();
    float sf2 = scc[0];
    float m = 0.f;
    uint4* swarp = sstage + wid * (32 * 9);
    uint4* smine = swarp + lane * 9;

#pragma unroll 1
    for (int wbase = blockIdx.x * 256 + wid * 32; wbase < rows; wbase += nt) {
        int nvalid = rows - wbase;
        if (nvalid > 32) nvalid = 32;
        load_tile<8, 9>(swarp, g_a2 + (size_t)wbase * 8, lane, nvalid);
        __syncwarp();
        if (lane < nvalid) {
            int q2[8];
#pragma unroll
            for (int c = 0; c < 8; c++) {
                uint4 v = smine[c];
                int ob = c * 4;
                q2[c] = pack4i(
                    fquant_pos2((float)(int)v.x, scf2[ob + 0], sf2),
                    fquant_pos2((float)(int)v.y, scf2[ob + 1], sf2),
                    fquant_pos2((float)(int)v.z, scf2[ob + 2], sf2),
                    fquant_pos2((float)(int)v.w, scf2[ob + 3], sf2));
            }
#pragma unroll
            for (int g = 0; g < 4; g++) {
                unsigned w[4];
#pragma unroll
                for (int j = 0; j < 4; j++) {
                    int o0 = g * 8 + 2 * j, o1 = o0 + 1;
                    int4 wa = sW3[o0 * 2], wb = sW3[o0 * 2 + 1];
                    int4 wc = sW3[o1 * 2], wd = sW3[o1 * 2 + 1];
                    int a0 = sb3[o0], a1 = sb3[o1];
                    a0 = dp4a_(q2[0], wa.x, a0); a0 = dp4a_(q2[1], wa.y, a0);
                    a0 = dp4a_(q2[2], wa.z, a0); a0 = dp4a_(q2[3], wa.w, a0);
                    a0 = dp4a_(q2[4], wb.x, a0); a0 = dp4a_(q2[5], wb.y, a0);
                    a0 = dp4a_(q2[6], wb.z, a0); a0 = dp4a_(q2[7], wb.w, a0);
                    a1 = dp4a_(q2[0], wc.x, a1); a1 = dp4a_(q2[1], wc.y, a1);
                    a1 = dp4a_(q2[2], wc.z, a1); a1 = dp4a_(q2[3], wc.w, a1);
                    a1 = dp4a_(q2[4], wd.x, a1); a1 = dp4a_(q2[5], wd.y, a1);
                    a1 = dp4a_(q2[6], wd.z, a1); a1 = dp4a_(q2[7], wd.w, a1);
                    m = fmaxf(m, __fmul_rn((float)a0, sbsf3[o0]));
                    m = fmaxf(m, __fmul_rn((float)a1, sbsf3[o1]));
                    w[j] = packh2(a0, a1);
                }
                smine[g] = make_uint4(w[0], w[1], w[2], w[3]);
            }
        }
        __syncwarp();
        flush_tile<4, 9>(g_a3 + (size_t)wbase * 4, swarp, lane, nvalid);
        __syncwarp();
    }
    warp_fmax_atomic(m, &g_hmax3);
}

// ---- K4b: sf3, cmb3, layer-4 bias quant -----------------------------------
__global__ void k4b_fin(const float* __restrict__ b4) {
    __shared__ float s_sf, s_inv;
    int t = threadIdx.x;  // 32 threads
    if (t == 0) {
        float sf = __fdiv_rn(fmaxf(__uint_as_float(g_hmax3), 1e-8f), 31.0f);
        g_sf3 = sf;
        s_sf = sf;
        s_inv = __fdiv_rn(1.0f, sf);
    }
    __syncthreads();
    g_cmb3[t] = __fmul_rn(g_bsf3[t], s_inv);
    if (t < 5) {
        float bsf = __fmul_rn(g_wsc4[t], s_sf);
        g_bsf4[t] = bsf;
        g_bint4[t] = iclamp((int)rintf(__fdiv_rn(b4[t], bsf)), -32, 31);
    }
}

// ---- K5: acc3 (staged in) -> q3 -> L4, softmax, staged store --------------
__global__ __launch_bounds__(256, 3) void k5_out(float* __restrict__ out,
                                                 int rows, int nt) {
    __shared__ int4 sW4[10];
    __shared__ int sb4[8];
    __shared__ float2 scf3[32];
    __shared__ float sbsf4[8], scc[1];
    __shared__ __align__(16) uint4 sain[8 * 32 * 5];   // 20,480 B a3 staging
    __shared__ __align__(16) float sobuf[1280];        // 256 rows x 5 probs
    int t = threadIdx.x;
    int wid = t >> 5, lane = t & 31;
    if (t < 10) sW4[t] = ((const int4*)g_W4p)[t];
    if (t < 32) scf3[t] = make_float2(g_cmb3[t], g_bsf3[t]);
    if (t < 5) { sb4[t] = g_bint4[t]; sbsf4[t] = g_bsf4[t]; }
    if (t == 0) scc[0] = g_sf3;
    __syncthreads();
    float sf3 = scc[0];
    uint4* swarp = sain + wid * (32 * 5);
    uint4* smine = swarp + lane * 5;

#pragma unroll 1
    for (int base = blockIdx.x * 256; base < rows; base += nt) {
        int wbase = base + wid * 32;
        int nvalid = rows - wbase;
        if (nvalid > 32) nvalid = 32;
        if (nvalid > 0) {
            load_tile<4, 5>(swarp, g_a3 + (size_t)wbase * 4, lane, nvalid);
        }
        __syncwarp();
        if (nvalid > 0 && lane < nvalid) {
            int q3[8];
#pragma unroll
            for (int c = 0; c < 4; c++) {
                uint4 v = smine[c];
                q3[c * 2 + 0] = quant4_i16(v.x, v.y, c * 8 + 0, scf3, sf3);
                q3[c * 2 + 1] = quant4_i16(v.z, v.w, c * 8 + 4, scf3, sf3);
            }
            float logit[5];
#pragma unroll
            for (int c = 0; c < 5; c++) {
                int4 wa = sW4[c * 2], wb = sW4[c * 2 + 1];
                int acc = sb4[c];
                acc = dp4a_(q3[0], wa.x, acc); acc = dp4a_(q3[1], wa.y, acc);
                acc = dp4a_(q3[2], wa.z, acc); acc = dp4a_(q3[3], wa.w, acc);
                acc = dp4a_(q3[4], wb.x, acc); acc = dp4a_(q3[5], wb.y, acc);
                acc = dp4a_(q3[6], wb.z, acc); acc = dp4a_(q3[7], wb.w, acc);
                logit[c] = __fmul_rn((float)acc, sbsf4[c]);
            }
            float mm = logit[0];
#pragma unroll
            for (int c = 1; c < 5; c++) mm = fmaxf(mm, logit[c]);
            float e[5], s = 0.f;
#pragma unroll
            for (int c = 0; c < 5; c++) { e[c] = __expf(logit[c] - mm); s += e[c]; }
            float rs = __frcp_rn(s);
#pragma unroll
            for (int c = 0; c < 5; c++) sobuf[t * 5 + c] = e[c] * rs;
        }
        __syncthreads();
        int n = rows - base;
        if (n > 256) n = 256;
        float* gbase = out + (size_t)base * 5;
        if (n == 256) {
            float4* g4 = (float4*)gbase;
            const float4* s4 = (const float4*)sobuf;
#pragma unroll
            for (int i = t; i < 320; i += 256) g4[i] = s4[i];
        } else {
            int n5 = n * 5;
            for (int i = t; i < n5; i += 256) gbase[i] = sobuf[i];
        }
        __syncthreads();
    }
}

// ---- launcher --------------------------------------------------------------
extern "C" void kernel_launch(void* const* d_in, const int* in_sizes, int n_in,
                              void* d_out, int out_size) {
    const float* x  = (const float*)d_in[0];
    const float* W1 = (const float*)d_in[1];
    const float* b1 = (const float*)d_in[2];
    const float* W2 = (const float*)d_in[3];
    const float* b2 = (const float*)d_in[4];
    const float* W3 = (const float*)d_in[5];
    const float* b3 = (const float*)d_in[6];
    const float* W4 = (const float*)d_in[7];
    const float* b4 = (const float*)d_in[8];
    float* out = (float*)d_out;

    int rows = in_sizes[0] / 16;
    if (rows > ROWS_CAP) rows = ROWS_CAP;

    int grid = (rows + 255) / 256;
    if (grid > 2368) grid = 2368;  // 148 SMs * 16 blocks
    int nt = grid * 256;

    k0_init<<<1, 256>>>(W1, W2, W3, W4);
    k1_absmax<<<2048, 256>>>(x, rows * 4);
    k1b_fin<<<1, 64>>>(b1);
    k2_l1<<<grid, 256>>>(x, rows, nt);
    k2b_fin<<<1, 64>>>(b2);
    k3_l2<<<grid, 256>>>(rows, nt);
    k3b_fin<<<1, 32>>>(b3);
    k4_l3<<<grid, 256>>>(rows, nt);
    k4b_fin<<<1, 32>>>(b4);
    k5_out<<<grid, 256>>>(out, rows, nt);
    (void)n_in; (void)out_size;
}